// round 12
// baseline (speedup 1.0000x reference)
#include <cuda_runtime.h>
#include <math.h>
#include <float.h>
#include <stdint.h>

#define DEPTH  6
#define DIM    1024
#define HEADS  16
#define DH     64
#define INNER  2730
#define INNER_P 2732
#define INNER2 5460
#define BATCH  2
#define SEQ    1024
#define TOK    (BATCH*SEQ)
#define NBUCK  32
#define QKV_N  1152   // 1024 q + 64 k + 64 v

// ---------------- scratch ----------------
__device__ float g_x  [TOK*DIM];
__device__ float g_h  [TOK*DIM];
__device__ float g_qkv[(size_t)TOK*QKV_N + 32];
__device__ float g_o  [TOK*DIM];
__device__ float g_g1 [(size_t)TOK*INNER2 + 32];
__device__ float g_h3 [(size_t)TOK*INNER_P + 32];
__device__ float g_bias[SEQ*HEADS];
__device__ float g_wqkv[(size_t)DEPTH*DIM*QKV_N];
__device__ float g_part[2*(size_t)TOK*QKV_N];

// ---------------- rel-pos bias ----------------
__global__ void bias_kernel(const float* __restrict__ rel_emb){
    int idx = blockIdx.x*blockDim.x + threadIdx.x;
    if (idx >= SEQ*HEADS) return;
    int delta = idx / HEADS;
    int h     = idx % HEADS;
    int bucket;
    if (delta < NBUCK/2) {
        bucket = delta;
    } else {
        float nf = (float)delta;
        int vl = (NBUCK/2) + (int)(logf(nf / (float)(NBUCK/2)) / logf(8.0f) * (float)(NBUCK/2));
        bucket = vl < (NBUCK-1) ? vl : (NBUCK-1);
    }
    g_bias[idx] = rel_emb[bucket*HEADS + h];
}

__global__ void scale_copy_kernel(const float* __restrict__ in, float* __restrict__ out, int n){
    int i = blockIdx.x*blockDim.x + threadIdx.x;
    if (i < n){ float v = in[i]; out[i] = v*0.1f + v*0.9f; }
}

// ---------------- pack wq|wkv into combined weight ----------------
__global__ void pack_qkv_kernel(const float* __restrict__ wq, const float* __restrict__ wkv,
                                float* __restrict__ wqkv){
    size_t i = (size_t)blockIdx.x*256 + threadIdx.x;
    if (i >= (size_t)DEPTH*DIM*QKV_N) return;
    int c = (int)(i % QKV_N);
    size_t rk = i / QKV_N;
    int k = (int)(rk % DIM);
    int l = (int)(rk / DIM);
    wqkv[i] = (c < DIM) ? wq[((size_t)l*DIM + k)*DIM + c]
                        : wkv[((size_t)l*DIM + k)*(2*DH) + (c - DIM)];
}

// ---------------- combine split-K partials: C = P0 + P1 (+R) ----------------
__global__ __launch_bounds__(256) void combine_kernel(const float* __restrict__ P,
                                                      const float* __restrict__ R,
                                                      float* __restrict__ C, int n4){
    int i = blockIdx.x*blockDim.x + threadIdx.x;
    if (i >= n4) return;
    const float4* P0 = reinterpret_cast<const float4*>(P);
    const float4* P1 = P0 + n4;
    float4 a = P0[i], b = P1[i];
    float4 v = make_float4(a.x+b.x, a.y+b.y, a.z+b.z, a.w+b.w);
    if (R){
        float4 r = reinterpret_cast<const float4*>(R)[i];
        v.x += r.x; v.y += r.y; v.z += r.z; v.w += r.w;
    }
    reinterpret_cast<float4*>(C)[i] = v;
}

// ---------------- LayerNorm specialized D=1024, 256 threads, float4 ----------------
__global__ __launch_bounds__(256) void ln1024_kernel(const float* __restrict__ in,
                                                     const float* __restrict__ g,
                                                     float* __restrict__ out){
    int t = blockIdx.x;
    const float4* row4 = reinterpret_cast<const float4*>(in + (size_t)t*DIM);
    float4 v = row4[threadIdx.x];
    float s  = v.x + v.y + v.z + v.w;
    float s2 = v.x*v.x + v.y*v.y + v.z*v.z + v.w*v.w;
    __shared__ float sh1[8], sh2[8];
    int lane = threadIdx.x & 31, warp = threadIdx.x >> 5;
    #pragma unroll
    for (int off = 16; off; off >>= 1){
        s  += __shfl_xor_sync(0xffffffffu, s,  off);
        s2 += __shfl_xor_sync(0xffffffffu, s2, off);
    }
    if (lane == 0){ sh1[warp] = s; sh2[warp] = s2; }
    __syncthreads();
    if (warp == 0){
        s  = (lane < 8) ? sh1[lane] : 0.f;
        s2 = (lane < 8) ? sh2[lane] : 0.f;
        #pragma unroll
        for (int off = 4; off; off >>= 1){
            s  += __shfl_xor_sync(0xffffffffu, s,  off);
            s2 += __shfl_xor_sync(0xffffffffu, s2, off);
        }
        if (lane == 0){ sh1[0] = s; sh2[0] = s2; }
    }
    __syncthreads();
    float m   = sh1[0] / (float)DIM;
    float var = sh2[0] / (float)DIM - m*m;
    float r   = rsqrtf(var + 1e-5f);
    const float4* g4 = reinterpret_cast<const float4*>(g);
    float4 gv = g4[threadIdx.x];
    float4 o;
    o.x = (v.x - m) * r * gv.x;
    o.y = (v.y - m) * r * gv.y;
    o.z = (v.z - m) * r * gv.z;
    o.w = (v.w - m) * r * gv.w;
    reinterpret_cast<float4*>(out + (size_t)t*DIM)[threadIdx.x] = o;
}

// ---------------- tf32 helpers ----------------
__device__ __forceinline__ float to_tf32(float x){
    uint32_t u; asm("cvt.rna.tf32.f32 %0, %1;" : "=r"(u) : "f"(x));
    return __uint_as_float(u);
}
__device__ __forceinline__ void mma_tf32(float* d, const uint32_t* a, const uint32_t* b){
    asm volatile(
        "mma.sync.aligned.m16n8k8.row.col.f32.tf32.tf32.f32 "
        "{%0,%1,%2,%3}, {%4,%5,%6,%7}, {%8,%9}, {%0,%1,%2,%3};\n"
        : "+f"(d[0]), "+f"(d[1]), "+f"(d[2]), "+f"(d[3])
        : "r"(a[0]), "r"(a[1]), "r"(a[2]), "r"(a[3]), "r"(b[0]), "r"(b[1]));
}

// ================= GEMM core (128x128, KT=16, double-buffered) =================
__device__ __forceinline__ void gemm_mainloop(const float* __restrict__ A,
                                              const float* __restrict__ W,
                                              float As[2][2048], float Bs[2][2048],
                                              int bm, int bn, int t,
                                              int K0, int Kend, int N, int lda,
                                              float acc[4][4][4]){
    const int lane = t & 31;
    const int warp = t >> 5;
    const int wm = warp >> 2;
    const int wn = warp & 3;

    float a_reg[2][4];
    float b_reg[8];
    int a_row[2], a_col[2];
    #pragma unroll
    for (int v = 0; v < 2; v++){
        int id = 2*t + v;
        int al = id & 31, mt = (id >> 5) & 7, g = id >> 8;
        a_row[v] = bm + mt*16 + (al >> 2);
        a_col[v] = g*8 + (al & 3);
    }
    int b_col[4], b_k[4];
    #pragma unroll
    for (int u = 0; u < 4; u++){
        int vid = 4*t + u;
        int lb = vid & 31, nt = (vid >> 5) & 15, g = vid >> 9;
        b_col[u] = bn + nt*8 + (lb >> 2);
        b_k[u]   = g*8 + (lb & 3);
    }

    const int ntiles = (Kend - K0 + 15) / 16;

    auto load_tile = [&](int k0){
        #pragma unroll
        for (int v = 0; v < 2; v++){
            const float* p = A + (size_t)a_row[v]*lda + k0 + a_col[v];
            a_reg[v][0] = p[0];
            a_reg[v][1] = p[(size_t)8*lda];
            a_reg[v][2] = p[4];
            a_reg[v][3] = p[(size_t)8*lda + 4];
        }
        #pragma unroll
        for (int u = 0; u < 4; u++){
            int kg = k0 + b_k[u];
            int cb = b_col[u];
            bool okc = (cb < N);
            b_reg[u*2+0] = (okc && kg     < Kend) ? W[(size_t)kg*N + cb]     : 0.f;
            b_reg[u*2+1] = (okc && kg + 4 < Kend) ? W[(size_t)(kg+4)*N + cb] : 0.f;
        }
    };
    auto store_tile = [&](int buf){
        #pragma unroll
        for (int v = 0; v < 2; v++){
            float4 q = make_float4(to_tf32(a_reg[v][0]), to_tf32(a_reg[v][1]),
                                   to_tf32(a_reg[v][2]), to_tf32(a_reg[v][3]));
            *reinterpret_cast<float4*>(&As[buf][(2*t + v)*4]) = q;
        }
        float4 q0 = make_float4(to_tf32(b_reg[0]), to_tf32(b_reg[1]),
                                to_tf32(b_reg[2]), to_tf32(b_reg[3]));
        float4 q1 = make_float4(to_tf32(b_reg[4]), to_tf32(b_reg[5]),
                                to_tf32(b_reg[6]), to_tf32(b_reg[7]));
        *reinterpret_cast<float4*>(&Bs[buf][8*t])     = q0;
        *reinterpret_cast<float4*>(&Bs[buf][8*t + 4]) = q1;
    };

    load_tile(K0);
    store_tile(0);
    __syncthreads();

    int buf = 0;
    for (int tile = 0; tile < ntiles; tile++){
        const bool more = (tile + 1 < ntiles);
        if (more) load_tile(K0 + (tile + 1) * 16);

        #pragma unroll
        for (int g = 0; g < 2; g++){
            uint32_t afr[4][4], bfr[4][2];
            #pragma unroll
            for (int i = 0; i < 4; i++)
                *reinterpret_cast<float4*>(afr[i]) =
                    *reinterpret_cast<const float4*>(&As[buf][((g*8 + wm*4 + i)*32 + lane)*4]);
            #pragma unroll
            for (int jn = 0; jn < 4; jn++)
                *reinterpret_cast<float2*>(bfr[jn]) =
                    *reinterpret_cast<const float2*>(&Bs[buf][((g*16 + wn*4 + jn)*32 + lane)*2]);
            #pragma unroll
            for (int i = 0; i < 4; i++)
                #pragma unroll
                for (int jn = 0; jn < 4; jn++)
                    mma_tf32(acc[i][jn], afr[i], bfr[jn]);
        }

        if (more) store_tile(buf ^ 1);
        __syncthreads();
        buf ^= 1;
    }
}

__device__ __forceinline__ void gemm_epilogue(float* __restrict__ C,
                                              const float* __restrict__ R,
                                              int bm, int bn, int t, int N,
                                              float acc[4][4][4]){
    const int lane = t & 31;
    const int warp = t >> 5;
    const int wm = warp >> 2;
    const int wn = warp & 3;
    const int r0 = bm + wm*64 + (lane >> 2);
    const int c0 = bn + wn*32 + (lane & 3)*2;
    #pragma unroll
    for (int i = 0; i < 4; i++){
        #pragma unroll
        for (int jn = 0; jn < 4; jn++){
            int col = c0 + jn*8;
            #pragma unroll
            for (int half = 0; half < 2; half++){
                int row = r0 + i*16 + half*8;
                size_t base = (size_t)row * N;
                float v0 = acc[i][jn][half*2 + 0];
                float v1 = acc[i][jn][half*2 + 1];
                if (col + 1 < N){
                    if (R){ v0 += R[base + col]; v1 += R[base + col + 1]; }
                    C[base + col]     = v0;
                    C[base + col + 1] = v1;
                } else if (col < N){
                    if (R) v0 += R[base + col];
                    C[base + col] = v0;
                }
            }
        }
    }
}

// ---------------- plain GEMM ----------------
__global__ __launch_bounds__(256, 2) void gemm_mma_kernel(const float* __restrict__ A,
                                                          const float* __restrict__ W,
                                                          const float* __restrict__ R,
                                                          float* __restrict__ C,
                                                          int M, int K, int N, int lda){
    __shared__ float As[2][2048];
    __shared__ float Bs[2][2048];
    const int bm = blockIdx.y * 128;
    const int bn = blockIdx.x * 128;
    const int t  = threadIdx.x;
    float acc[4][4][4];
    #pragma unroll
    for (int i = 0; i < 4; i++)
        #pragma unroll
        for (int j = 0; j < 4; j++)
            #pragma unroll
            for (int q = 0; q < 4; q++) acc[i][j][q] = 0.f;
    gemm_mainloop(A, W, As, Bs, bm, bn, t, 0, K, N, lda, acc);
    gemm_epilogue(C, R, bm, bn, t, N, acc);
}

// ---------------- split-K GEMM ----------------
__global__ __launch_bounds__(256, 2) void gemm_mma_splitk_kernel(const float* __restrict__ A,
                                                                 const float* __restrict__ W,
                                                                 float* __restrict__ Cpart,
                                                                 int M, int K, int KH,
                                                                 int N, int lda){
    __shared__ float As[2][2048];
    __shared__ float Bs[2][2048];
    const int bm = blockIdx.y * 128;
    const int bn = blockIdx.x * 128;
    const int t  = threadIdx.x;
    const int z  = blockIdx.z;
    const int K0   = z * KH;
    const int Kend = (K0 + KH < K) ? (K0 + KH) : K;
    float acc[4][4][4];
    #pragma unroll
    for (int i = 0; i < 4; i++)
        #pragma unroll
        for (int j = 0; j < 4; j++)
            #pragma unroll
            for (int q = 0; q < 4; q++) acc[i][j][q] = 0.f;
    gemm_mainloop(A, W, As, Bs, bm, bn, t, K0, Kend, N, lda, acc);
    gemm_epilogue(Cpart + (size_t)z*M*N, nullptr, bm, bn, t, N, acc);
}

// ---------------- fused attention: reg-Q, single-exp softmax, deferred norm ----------------
#define AT_ROWS 16
#define KV_LD 68
#define ATTN_SMEM ((AT_ROWS*SEQ + 2*64*KV_LD + 32) * (int)sizeof(float))

__global__ __launch_bounds__(256) void attn_kernel(const float* __restrict__ qkv,
                                                   float* __restrict__ o){
    extern __shared__ float sm[];
    float* S    = sm;                     // 16 x SEQ (unnormalized p after softmax pass)
    float* Ks   = S  + AT_ROWS*SEQ;       // 64 x KV_LD
    float* Vs   = Ks + 64*KV_LD;          // 64 x KV_LD
    float* Sinv = Vs + 64*KV_LD;          // 16 row inverses
    int it = blockIdx.x;
    int h  = blockIdx.y;
    int b  = blockIdx.z;
    int i0 = it * AT_ROWS;
    int tid = threadIdx.x;
    int row = tid >> 4;
    int q16 = tid & 15;
    int i   = i0 + row;

    float4 qreg[16];
    {
        const float4* qp = reinterpret_cast<const float4*>(
            qkv + (size_t)(b*SEQ + i)*QKV_N + h*DH);
        #pragma unroll
        for (int c = 0; c < 16; c++){
            float4 v = qp[c];
            v.x *= 0.125f; v.y *= 0.125f; v.z *= 0.125f; v.w *= 0.125f;
            qreg[c] = v;
        }
    }

    int njt = (i0 + AT_ROWS - 1)/64 + 1;

    // ---- scores ----
    for (int jt = 0; jt < njt; jt++){
        for (int idx = tid; idx < 64*16; idx += 256){
            int r = idx >> 4, c4 = idx & 15;
            float4 v = *reinterpret_cast<const float4*>(
                qkv + (size_t)(b*SEQ + jt*64 + r)*QKV_N + DIM + c4*4);
            *reinterpret_cast<float4*>(&Ks[r*KV_LD + c4*4]) = v;
        }
        __syncthreads();
        #pragma unroll
        for (int jj = 0; jj < 4; jj++){
            int jl = jj*16 + q16;
            int j  = jt*64 + jl;
            float acc = 0.f;
            #pragma unroll
            for (int c = 0; c < 16; c++){
                float4 k4 = *reinterpret_cast<const float4*>(&Ks[jl*KV_LD + c*4]);
                acc += qreg[c].x*k4.x + qreg[c].y*k4.y + qreg[c].z*k4.z + qreg[c].w*k4.w;
            }
            S[row*SEQ + j] = (j <= i) ? (acc + g_bias[(i-j)*HEADS + h]) : -FLT_MAX;
        }
        __syncthreads();
    }

    // ---- softmax pass: p = exp(S-mx) stored unnormalized; 1/sum kept per row ----
    int warp = tid >> 5, lane = tid & 31;
    int ncol = njt * 64;
    for (int r = warp*2; r < warp*2 + 2; r++){
        int ii = i0 + r;
        float mx = -FLT_MAX;
        for (int j = lane; j <= ii; j += 32) mx = fmaxf(mx, S[r*SEQ + j]);
        #pragma unroll
        for (int off = 16; off; off >>= 1) mx = fmaxf(mx, __shfl_xor_sync(0xffffffffu, mx, off));
        float sum = 0.f;
        for (int j = lane; j < ncol; j += 32){
            float p = __expf(S[r*SEQ + j] - mx);   // masked cells (-FLT_MAX) -> 0
            S[r*SEQ + j] = p;
            sum += p;
        }
        #pragma unroll
        for (int off = 16; off; off >>= 1) sum += __shfl_xor_sync(0xffffffffu, sum, off);
        if (lane == 0) Sinv[r] = 1.f / sum;
    }
    __syncthreads();

    // ---- attn @ V with float4 S loads; normalize at the end ----
    float4 accv = make_float4(0.f, 0.f, 0.f, 0.f);
    for (int jt = 0; jt < njt; jt++){
        for (int idx = tid; idx < 64*16; idx += 256){
            int r = idx >> 4, c4 = idx & 15;
            float4 v = *reinterpret_cast<const float4*>(
                qkv + (size_t)(b*SEQ + jt*64 + r)*QKV_N + DIM + DH + c4*4);
            *reinterpret_cast<float4*>(&Vs[r*KV_LD + c4*4]) = v;
        }
        __syncthreads();
        #pragma unroll 4
        for (int j4 = 0; j4 < 16; j4++){
            float4 s4 = *reinterpret_cast<const float4*>(&S[row*SEQ + jt*64 + j4*4]);
            float4 v0 = *reinterpret_cast<const float4*>(&Vs[(j4*4+0)*KV_LD + q16*4]);
            float4 v1 = *reinterpret_cast<const float4*>(&Vs[(j4*4+1)*KV_LD + q16*4]);
            float4 v2 = *reinterpret_cast<const float4*>(&Vs[(j4*4+2)*KV_LD + q16*4]);
            float4 v3 = *reinterpret_cast<const float4*>(&Vs[(j4*4+3)*KV_LD + q16*4]);
            accv.x += s4.x*v0.x + s4.y*v1.x + s4.z*v2.x + s4.w*v3.x;
            accv.y += s4.x*v0.y + s4.y*v1.y + s4.z*v2.y + s4.w*v3.y;
            accv.z += s4.x*v0.z + s4.y*v1.z + s4.z*v2.z + s4.w*v3.z;
            accv.w += s4.x*v0.w + s4.y*v1.w + s4.z*v2.w + s4.w*v3.w;
        }
        __syncthreads();
    }
    float inv = Sinv[row];
    accv.x *= inv; accv.y *= inv; accv.z *= inv; accv.w *= inv;
    *reinterpret_cast<float4*>(o + (size_t)(b*SEQ + i)*DIM + h*DH + q16*4) = accv;
}

// ---------------- fused causal conv(3) + GELU-GLU + LayerNorm ----------------
__global__ __launch_bounds__(256) void convglu_ln_kernel(const float* __restrict__ g1,
                                                         const float* __restrict__ cw,
                                                         const float* __restrict__ lng,
                                                         float* __restrict__ out){
    __shared__ float hbuf[INNER];
    __shared__ float sh1[8], sh2[8];
    int t = blockIdx.x;
    int n = t & (SEQ-1);
    size_t base = (size_t)t * INNER2;
    float s = 0.f, s2 = 0.f;
    for (int c = threadIdx.x; c < INNER; c += blockDim.x){
        float w0 = cw[c*3+0], w1 = cw[c*3+1], w2 = cw[c*3+2];
        float a = ((n >= 2) ? g1[base - 2*(size_t)INNER2 + c] : 0.f) * w0
                + ((n >= 1) ? g1[base -   (size_t)INNER2 + c] : 0.f) * w1
                +              g1[base + c] * w2;
        int cg = c + INNER;
        float v0 = cw[cg*3+0], v1 = cw[cg*3+1], v2 = cw[cg*3+2];
        float g = ((n >= 2) ? g1[base - 2*(size_t)INNER2 + cg] : 0.f) * v0
                + ((n >= 1) ? g1[base -   (size_t)INNER2 + cg] : 0.f) * v1
                +              g1[base + cg] * v2;
        float gg = 0.5f * g * (1.f + erff(g * 0.70710678118654752f));
        float h = gg * a;
        hbuf[c] = h;
        s += h; s2 += h*h;
    }
    int lane = threadIdx.x & 31, warp = threadIdx.x >> 5;
    #pragma unroll
    for (int off = 16; off; off >>= 1){
        s  += __shfl_xor_sync(0xffffffffu, s,  off);
        s2 += __shfl_xor_sync(0xffffffffu, s2, off);
    }
    if (lane == 0){ sh1[warp] = s; sh2[warp] = s2; }
    __syncthreads();
    if (warp == 0){
        s  = (lane < 8) ? sh1[lane] : 0.f;
        s2 = (lane < 8) ? sh2[lane] : 0.f;
        #pragma unroll
        for (int off = 4; off; off >>= 1){
            s  += __shfl_xor_sync(0xffffffffu, s,  off);
            s2 += __shfl_xor_sync(0xffffffffu, s2, off);
        }
        if (lane == 0){ sh1[0] = s; sh2[0] = s2; }
    }
    __syncthreads();
    float m   = sh1[0] / (float)INNER;
    float var = sh2[0] / (float)INNER - m*m;
    float r   = rsqrtf(var + 1e-5f);
    for (int c = threadIdx.x; c < INNER; c += blockDim.x)
        out[(size_t)t*INNER_P + c] = (hbuf[c] - m) * r * lng[c];
    for (int c = INNER + threadIdx.x; c < INNER_P; c += blockDim.x)
        out[(size_t)t*INNER_P + c] = 0.f;
}

// ---------------- launch helpers ----------------
static inline void run_gemm(const float* A, const float* W, const float* R, float* C,
                            int M, int K, int N, int lda){
    dim3 grid((N + 127)/128, M/128);
    gemm_mma_kernel<<<grid, 256>>>(A, W, R, C, M, K, N, lda);
}
static inline void run_gemm_splitk(const float* A, const float* W, float* Cpart,
                                   const float* R, float* C,
                                   int M, int K, int KH, int N, int lda){
    dim3 grid((N + 127)/128, M/128, 2);
    gemm_mma_splitk_kernel<<<grid, 256>>>(A, W, Cpart, M, K, KH, N, lda);
    int n4 = (int)(((size_t)M*N) >> 2);
    combine_kernel<<<(n4 + 255)/256, 256>>>(Cpart, R, C, n4);
}

extern "C" void kernel_launch(void* const* d_in, const int* in_sizes, int n_in,
                              void* d_out, int out_size){
    const float* x     = (const float*)d_in[0];
    const float* rel   = (const float*)d_in[1];
    const float* qn_g  = (const float*)d_in[2];
    const float* wq    = (const float*)d_in[3];
    const float* wkv   = (const float*)d_in[4];
    const float* wo    = (const float*)d_in[5];
    const float* ln1g  = (const float*)d_in[6];
    const float* w1    = (const float*)d_in[7];
    const float* convw = (const float*)d_in[8];
    const float* ln2g  = (const float*)d_in[9];
    const float* w2    = (const float*)d_in[10];
    const float* fing  = (const float*)d_in[11];
    float* out = (float*)d_out;

    float *px, *ph, *pqkv, *po, *pg1, *ph3, *pwqkv, *ppart;
    cudaGetSymbolAddress((void**)&px,    g_x);
    cudaGetSymbolAddress((void**)&ph,    g_h);
    cudaGetSymbolAddress((void**)&pqkv,  g_qkv);
    cudaGetSymbolAddress((void**)&po,    g_o);
    cudaGetSymbolAddress((void**)&pg1,   g_g1);
    cudaGetSymbolAddress((void**)&ph3,   g_h3);
    cudaGetSymbolAddress((void**)&pwqkv, g_wqkv);
    cudaGetSymbolAddress((void**)&ppart, g_part);

    cudaFuncSetAttribute(attn_kernel, cudaFuncAttributeMaxDynamicSharedMemorySize, ATTN_SMEM);

    bias_kernel<<<(SEQ*HEADS + 255)/256, 256>>>(rel);
    scale_copy_kernel<<<(TOK*DIM + 255)/256, 256>>>(x, px, TOK*DIM);
    {
        size_t tot = (size_t)DEPTH*DIM*QKV_N;
        pack_qkv_kernel<<<(unsigned)((tot + 255)/256), 256>>>(wq, wkv, pwqkv);
    }

    for (int l = 0; l < DEPTH; l++){
        // attention block
        ln1024_kernel<<<TOK, 256>>>(px, qn_g + l*DIM, ph);
        run_gemm_splitk(ph, pwqkv + (size_t)l*DIM*QKV_N, ppart, nullptr, pqkv,
                        TOK, DIM, 512, QKV_N, DIM);
        dim3 agrid(SEQ/AT_ROWS, HEADS, BATCH);
        attn_kernel<<<agrid, 256, ATTN_SMEM>>>(pqkv, po);
        run_gemm_splitk(po, wo + (size_t)l*DIM*DIM, ppart, px, px,
                        TOK, DIM, 512, DIM, DIM);

        // conv-GLU MLP block
        ln1024_kernel<<<TOK, 256>>>(px, ln1g + l*DIM, ph);
        run_gemm(ph, w1 + (size_t)l*DIM*INNER2, nullptr, pg1, TOK, DIM, INNER2, DIM);
        convglu_ln_kernel<<<TOK, 256>>>(pg1, convw + (size_t)l*INNER2*3,
                                        ln2g + (size_t)l*INNER, ph3);
        run_gemm_splitk(ph3, w2 + (size_t)l*INNER*DIM, ppart, px, px,
                        TOK, INNER, 1376, DIM, INNER_P);
    }
    ln1024_kernel<<<TOK, 256>>>(px, fing, out);
}

// round 13
// speedup vs baseline: 1.5293x; 1.5293x over previous
#include <cuda_runtime.h>
#include <math.h>
#include <float.h>
#include <stdint.h>

#define DEPTH  6
#define DIM    1024
#define HEADS  16
#define DH     64
#define INNER  2730
#define INNER_P 2732
#define INNER2 5460
#define BATCH  2
#define SEQ    1024
#define TOK    (BATCH*SEQ)
#define NBUCK  32
#define QKV_N  1152   // 1024 q + 64 k + 64 v

// ---------------- scratch ----------------
__device__ float g_x  [TOK*DIM];
__device__ float g_h  [TOK*DIM];
__device__ float g_qkv[(size_t)TOK*QKV_N + 32];
__device__ float g_o  [TOK*DIM];
__device__ float g_g1 [(size_t)TOK*INNER2 + 32];
__device__ float g_h3 [(size_t)TOK*INNER_P + 32];
__device__ float g_bias[SEQ*HEADS];
__device__ float g_wqkv[(size_t)DEPTH*DIM*QKV_N];
__device__ float g_part[2*(size_t)TOK*QKV_N];

// ---------------- rel-pos bias ----------------
__global__ void bias_kernel(const float* __restrict__ rel_emb){
    int idx = blockIdx.x*blockDim.x + threadIdx.x;
    if (idx >= SEQ*HEADS) return;
    int delta = idx / HEADS;
    int h     = idx % HEADS;
    int bucket;
    if (delta < NBUCK/2) {
        bucket = delta;
    } else {
        float nf = (float)delta;
        int vl = (NBUCK/2) + (int)(logf(nf / (float)(NBUCK/2)) / logf(8.0f) * (float)(NBUCK/2));
        bucket = vl < (NBUCK-1) ? vl : (NBUCK-1);
    }
    g_bias[idx] = rel_emb[bucket*HEADS + h];
}

__global__ void scale_copy_kernel(const float* __restrict__ in, float* __restrict__ out, int n){
    int i = blockIdx.x*blockDim.x + threadIdx.x;
    if (i < n){ float v = in[i]; out[i] = v*0.1f + v*0.9f; }
}

// ---------------- pack wq|wkv into combined weight ----------------
__global__ void pack_qkv_kernel(const float* __restrict__ wq, const float* __restrict__ wkv,
                                float* __restrict__ wqkv){
    size_t i = (size_t)blockIdx.x*256 + threadIdx.x;
    if (i >= (size_t)DEPTH*DIM*QKV_N) return;
    int c = (int)(i % QKV_N);
    size_t rk = i / QKV_N;
    int k = (int)(rk % DIM);
    int l = (int)(rk / DIM);
    wqkv[i] = (c < DIM) ? wq[((size_t)l*DIM + k)*DIM + c]
                        : wkv[((size_t)l*DIM + k)*(2*DH) + (c - DIM)];
}

// ---------------- combine split-K partials: C = P0 + P1 (+R) ----------------
__global__ __launch_bounds__(256) void combine_kernel(const float* __restrict__ P,
                                                      const float* __restrict__ R,
                                                      float* __restrict__ C, int n4){
    int i = blockIdx.x*blockDim.x + threadIdx.x;
    if (i >= n4) return;
    const float4* P0 = reinterpret_cast<const float4*>(P);
    const float4* P1 = P0 + n4;
    float4 a = P0[i], b = P1[i];
    float4 v = make_float4(a.x+b.x, a.y+b.y, a.z+b.z, a.w+b.w);
    if (R){
        float4 r = reinterpret_cast<const float4*>(R)[i];
        v.x += r.x; v.y += r.y; v.z += r.z; v.w += r.w;
    }
    reinterpret_cast<float4*>(C)[i] = v;
}

// ---------------- LayerNorm specialized D=1024, 256 threads, float4 ----------------
__global__ __launch_bounds__(256) void ln1024_kernel(const float* __restrict__ in,
                                                     const float* __restrict__ g,
                                                     float* __restrict__ out){
    int t = blockIdx.x;
    const float4* row4 = reinterpret_cast<const float4*>(in + (size_t)t*DIM);
    float4 v = row4[threadIdx.x];
    float s  = v.x + v.y + v.z + v.w;
    float s2 = v.x*v.x + v.y*v.y + v.z*v.z + v.w*v.w;
    __shared__ float sh1[8], sh2[8];
    int lane = threadIdx.x & 31, warp = threadIdx.x >> 5;
    #pragma unroll
    for (int off = 16; off; off >>= 1){
        s  += __shfl_xor_sync(0xffffffffu, s,  off);
        s2 += __shfl_xor_sync(0xffffffffu, s2, off);
    }
    if (lane == 0){ sh1[warp] = s; sh2[warp] = s2; }
    __syncthreads();
    if (warp == 0){
        s  = (lane < 8) ? sh1[lane] : 0.f;
        s2 = (lane < 8) ? sh2[lane] : 0.f;
        #pragma unroll
        for (int off = 4; off; off >>= 1){
            s  += __shfl_xor_sync(0xffffffffu, s,  off);
            s2 += __shfl_xor_sync(0xffffffffu, s2, off);
        }
        if (lane == 0){ sh1[0] = s; sh2[0] = s2; }
    }
    __syncthreads();
    float m   = sh1[0] / (float)DIM;
    float var = sh2[0] / (float)DIM - m*m;
    float r   = rsqrtf(var + 1e-5f);
    const float4* g4 = reinterpret_cast<const float4*>(g);
    float4 gv = g4[threadIdx.x];
    float4 o;
    o.x = (v.x - m) * r * gv.x;
    o.y = (v.y - m) * r * gv.y;
    o.z = (v.z - m) * r * gv.z;
    o.w = (v.w - m) * r * gv.w;
    reinterpret_cast<float4*>(out + (size_t)t*DIM)[threadIdx.x] = o;
}

// ---------------- tf32 helpers ----------------
__device__ __forceinline__ float to_tf32(float x){
    uint32_t u; asm("cvt.rna.tf32.f32 %0, %1;" : "=r"(u) : "f"(x));
    return __uint_as_float(u);
}
__device__ __forceinline__ void mma_tf32(float* d, const uint32_t* a, const uint32_t* b){
    asm volatile(
        "mma.sync.aligned.m16n8k8.row.col.f32.tf32.tf32.f32 "
        "{%0,%1,%2,%3}, {%4,%5,%6,%7}, {%8,%9}, {%0,%1,%2,%3};\n"
        : "+f"(d[0]), "+f"(d[1]), "+f"(d[2]), "+f"(d[3])
        : "r"(a[0]), "r"(a[1]), "r"(a[2]), "r"(a[3]), "r"(b[0]), "r"(b[1]));
}

// ================= GEMM core (128x128, KT=16, double-buffered) =================
__device__ __forceinline__ void gemm_mainloop(const float* __restrict__ A,
                                              const float* __restrict__ W,
                                              float As[2][2048], float Bs[2][2048],
                                              int bm, int bn, int t,
                                              int K0, int Kend, int N, int lda,
                                              float acc[4][4][4]){
    const int lane = t & 31;
    const int warp = t >> 5;
    const int wm = warp >> 2;
    const int wn = warp & 3;

    float a_reg[2][4];
    float b_reg[8];
    int a_row[2], a_col[2];
    #pragma unroll
    for (int v = 0; v < 2; v++){
        int id = 2*t + v;
        int al = id & 31, mt = (id >> 5) & 7, g = id >> 8;
        a_row[v] = bm + mt*16 + (al >> 2);
        a_col[v] = g*8 + (al & 3);
    }
    int b_col[4], b_k[4];
    #pragma unroll
    for (int u = 0; u < 4; u++){
        int vid = 4*t + u;
        int lb = vid & 31, nt = (vid >> 5) & 15, g = vid >> 9;
        b_col[u] = bn + nt*8 + (lb >> 2);
        b_k[u]   = g*8 + (lb & 3);
    }

    const int ntiles = (Kend - K0 + 15) / 16;

    auto load_tile = [&](int k0){
        #pragma unroll
        for (int v = 0; v < 2; v++){
            const float* p = A + (size_t)a_row[v]*lda + k0 + a_col[v];
            a_reg[v][0] = p[0];
            a_reg[v][1] = p[(size_t)8*lda];
            a_reg[v][2] = p[4];
            a_reg[v][3] = p[(size_t)8*lda + 4];
        }
        #pragma unroll
        for (int u = 0; u < 4; u++){
            int kg = k0 + b_k[u];
            int cb = b_col[u];
            bool okc = (cb < N);
            b_reg[u*2+0] = (okc && kg     < Kend) ? W[(size_t)kg*N + cb]     : 0.f;
            b_reg[u*2+1] = (okc && kg + 4 < Kend) ? W[(size_t)(kg+4)*N + cb] : 0.f;
        }
    };
    auto store_tile = [&](int buf){
        #pragma unroll
        for (int v = 0; v < 2; v++){
            float4 q = make_float4(to_tf32(a_reg[v][0]), to_tf32(a_reg[v][1]),
                                   to_tf32(a_reg[v][2]), to_tf32(a_reg[v][3]));
            *reinterpret_cast<float4*>(&As[buf][(2*t + v)*4]) = q;
        }
        float4 q0 = make_float4(to_tf32(b_reg[0]), to_tf32(b_reg[1]),
                                to_tf32(b_reg[2]), to_tf32(b_reg[3]));
        float4 q1 = make_float4(to_tf32(b_reg[4]), to_tf32(b_reg[5]),
                                to_tf32(b_reg[6]), to_tf32(b_reg[7]));
        *reinterpret_cast<float4*>(&Bs[buf][8*t])     = q0;
        *reinterpret_cast<float4*>(&Bs[buf][8*t + 4]) = q1;
    };

    load_tile(K0);
    store_tile(0);
    __syncthreads();

    int buf = 0;
    for (int tile = 0; tile < ntiles; tile++){
        const bool more = (tile + 1 < ntiles);
        if (more) load_tile(K0 + (tile + 1) * 16);

        #pragma unroll
        for (int g = 0; g < 2; g++){
            uint32_t afr[4][4], bfr[4][2];
            #pragma unroll
            for (int i = 0; i < 4; i++)
                *reinterpret_cast<float4*>(afr[i]) =
                    *reinterpret_cast<const float4*>(&As[buf][((g*8 + wm*4 + i)*32 + lane)*4]);
            #pragma unroll
            for (int jn = 0; jn < 4; jn++)
                *reinterpret_cast<float2*>(bfr[jn]) =
                    *reinterpret_cast<const float2*>(&Bs[buf][((g*16 + wn*4 + jn)*32 + lane)*2]);
            #pragma unroll
            for (int i = 0; i < 4; i++)
                #pragma unroll
                for (int jn = 0; jn < 4; jn++)
                    mma_tf32(acc[i][jn], afr[i], bfr[jn]);
        }

        if (more) store_tile(buf ^ 1);
        __syncthreads();
        buf ^= 1;
    }
}

__device__ __forceinline__ void gemm_epilogue(float* __restrict__ C,
                                              const float* __restrict__ R,
                                              int bm, int bn, int t, int N,
                                              float acc[4][4][4]){
    const int lane = t & 31;
    const int warp = t >> 5;
    const int wm = warp >> 2;
    const int wn = warp & 3;
    const int r0 = bm + wm*64 + (lane >> 2);
    const int c0 = bn + wn*32 + (lane & 3)*2;
    #pragma unroll
    for (int i = 0; i < 4; i++){
        #pragma unroll
        for (int jn = 0; jn < 4; jn++){
            int col = c0 + jn*8;
            #pragma unroll
            for (int half = 0; half < 2; half++){
                int row = r0 + i*16 + half*8;
                size_t base = (size_t)row * N;
                float v0 = acc[i][jn][half*2 + 0];
                float v1 = acc[i][jn][half*2 + 1];
                if (col + 1 < N){
                    if (R){ v0 += R[base + col]; v1 += R[base + col + 1]; }
                    C[base + col]     = v0;
                    C[base + col + 1] = v1;
                } else if (col < N){
                    if (R) v0 += R[base + col];
                    C[base + col] = v0;
                }
            }
        }
    }
}

// ---------------- plain GEMM ----------------
__global__ __launch_bounds__(256, 2) void gemm_mma_kernel(const float* __restrict__ A,
                                                          const float* __restrict__ W,
                                                          const float* __restrict__ R,
                                                          float* __restrict__ C,
                                                          int M, int K, int N, int lda){
    __shared__ float As[2][2048];
    __shared__ float Bs[2][2048];
    const int bm = blockIdx.y * 128;
    const int bn = blockIdx.x * 128;
    const int t  = threadIdx.x;
    float acc[4][4][4];
    #pragma unroll
    for (int i = 0; i < 4; i++)
        #pragma unroll
        for (int j = 0; j < 4; j++)
            #pragma unroll
            for (int q = 0; q < 4; q++) acc[i][j][q] = 0.f;
    gemm_mainloop(A, W, As, Bs, bm, bn, t, 0, K, N, lda, acc);
    gemm_epilogue(C, R, bm, bn, t, N, acc);
}

// ---------------- split-K GEMM ----------------
__global__ __launch_bounds__(256, 2) void gemm_mma_splitk_kernel(const float* __restrict__ A,
                                                                 const float* __restrict__ W,
                                                                 float* __restrict__ Cpart,
                                                                 int M, int K, int KH,
                                                                 int N, int lda){
    __shared__ float As[2][2048];
    __shared__ float Bs[2][2048];
    const int bm = blockIdx.y * 128;
    const int bn = blockIdx.x * 128;
    const int t  = threadIdx.x;
    const int z  = blockIdx.z;
    const int K0   = z * KH;
    const int Kend = (K0 + KH < K) ? (K0 + KH) : K;
    float acc[4][4][4];
    #pragma unroll
    for (int i = 0; i < 4; i++)
        #pragma unroll
        for (int j = 0; j < 4; j++)
            #pragma unroll
            for (int q = 0; q < 4; q++) acc[i][j][q] = 0.f;
    gemm_mainloop(A, W, As, Bs, bm, bn, t, K0, Kend, N, lda, acc);
    gemm_epilogue(Cpart + (size_t)z*M*N, nullptr, bm, bn, t, N, acc);
}

// ---------------- fused attention: reg-Q, single-exp softmax, deferred norm ----------------
#define AT_ROWS 16
#define KV_LD 68
#define ATTN_SMEM ((AT_ROWS*SEQ + 2*64*KV_LD + 32) * (int)sizeof(float))

__global__ __launch_bounds__(256) void attn_kernel(const float* __restrict__ qkv,
                                                   float* __restrict__ o){
    extern __shared__ float sm[];
    float* S    = sm;                     // 16 x SEQ (unnormalized p after softmax pass)
    float* Ks   = S  + AT_ROWS*SEQ;       // 64 x KV_LD
    float* Vs   = Ks + 64*KV_LD;          // 64 x KV_LD
    float* Sinv = Vs + 64*KV_LD;          // 16 row inverses
    int it = blockIdx.x;
    int h  = blockIdx.y;
    int b  = blockIdx.z;
    int i0 = it * AT_ROWS;
    int tid = threadIdx.x;
    int row = tid >> 4;
    int q16 = tid & 15;
    int i   = i0 + row;

    float4 qreg[16];
    {
        const float4* qp = reinterpret_cast<const float4*>(
            qkv + (size_t)(b*SEQ + i)*QKV_N + h*DH);
        #pragma unroll
        for (int c = 0; c < 16; c++){
            float4 v = qp[c];
            v.x *= 0.125f; v.y *= 0.125f; v.z *= 0.125f; v.w *= 0.125f;
            qreg[c] = v;
        }
    }

    int njt = (i0 + AT_ROWS - 1)/64 + 1;

    // ---- scores ----
    for (int jt = 0; jt < njt; jt++){
        for (int idx = tid; idx < 64*16; idx += 256){
            int r = idx >> 4, c4 = idx & 15;
            float4 v = *reinterpret_cast<const float4*>(
                qkv + (size_t)(b*SEQ + jt*64 + r)*QKV_N + DIM + c4*4);
            *reinterpret_cast<float4*>(&Ks[r*KV_LD + c4*4]) = v;
        }
        __syncthreads();
        #pragma unroll
        for (int jj = 0; jj < 4; jj++){
            int jl = jj*16 + q16;
            int j  = jt*64 + jl;
            float acc = 0.f;
            #pragma unroll
            for (int c = 0; c < 16; c++){
                float4 k4 = *reinterpret_cast<const float4*>(&Ks[jl*KV_LD + c*4]);
                acc += qreg[c].x*k4.x + qreg[c].y*k4.y + qreg[c].z*k4.z + qreg[c].w*k4.w;
            }
            S[row*SEQ + j] = (j <= i) ? (acc + g_bias[(i-j)*HEADS + h]) : -FLT_MAX;
        }
        __syncthreads();
    }

    // ---- softmax pass: p = exp(S-mx) stored unnormalized; 1/sum kept per row ----
    int warp = tid >> 5, lane = tid & 31;
    int ncol = njt * 64;
    for (int r = warp*2; r < warp*2 + 2; r++){
        int ii = i0 + r;
        float mx = -FLT_MAX;
        for (int j = lane; j <= ii; j += 32) mx = fmaxf(mx, S[r*SEQ + j]);
        #pragma unroll
        for (int off = 16; off; off >>= 1) mx = fmaxf(mx, __shfl_xor_sync(0xffffffffu, mx, off));
        float sum = 0.f;
        for (int j = lane; j < ncol; j += 32){
            float p = __expf(S[r*SEQ + j] - mx);   // masked cells (-FLT_MAX) -> 0
            S[r*SEQ + j] = p;
            sum += p;
        }
        #pragma unroll
        for (int off = 16; off; off >>= 1) sum += __shfl_xor_sync(0xffffffffu, sum, off);
        if (lane == 0) Sinv[r] = __frcp_rn(sum);
    }
    __syncthreads();

    // ---- attn @ V with float4 S loads; normalize at the end ----
    float4 accv = make_float4(0.f, 0.f, 0.f, 0.f);
    for (int jt = 0; jt < njt; jt++){
        for (int idx = tid; idx < 64*16; idx += 256){
            int r = idx >> 4, c4 = idx & 15;
            float4 v = *reinterpret_cast<const float4*>(
                qkv + (size_t)(b*SEQ + jt*64 + r)*QKV_N + DIM + DH + c4*4);
            *reinterpret_cast<float4*>(&Vs[r*KV_LD + c4*4]) = v;
        }
        __syncthreads();
        #pragma unroll 4
        for (int j4 = 0; j4 < 16; j4++){
            float4 s4 = *reinterpret_cast<const float4*>(&S[row*SEQ + jt*64 + j4*4]);
            float4 v0 = *reinterpret_cast<const float4*>(&Vs[(j4*4+0)*KV_LD + q16*4]);
            float4 v1 = *reinterpret_cast<const float4*>(&Vs[(j4*4+1)*KV_LD + q16*4]);
            float4 v2 = *reinterpret_cast<const float4*>(&Vs[(j4*4+2)*KV_LD + q16*4]);
            float4 v3 = *reinterpret_cast<const float4*>(&Vs[(j4*4+3)*KV_LD + q16*4]);
            accv.x += s4.x*v0.x + s4.y*v1.x + s4.z*v2.x + s4.w*v3.x;
            accv.y += s4.x*v0.y + s4.y*v1.y + s4.z*v2.y + s4.w*v3.y;
            accv.z += s4.x*v0.z + s4.y*v1.z + s4.z*v2.z + s4.w*v3.z;
            accv.w += s4.x*v0.w + s4.y*v1.w + s4.z*v2.w + s4.w*v3.w;
        }
        __syncthreads();
    }
    float inv = Sinv[row];
    accv.x *= inv; accv.y *= inv; accv.z *= inv; accv.w *= inv;
    *reinterpret_cast<float4*>(o + (size_t)(b*SEQ + i)*DIM + h*DH + q16*4) = accv;
}

// ---------------- fused causal conv(3) + GELU-GLU + LayerNorm ----------------
__global__ __launch_bounds__(256) void convglu_ln_kernel(const float* __restrict__ g1,
                                                         const float* __restrict__ cw,
                                                         const float* __restrict__ lng,
                                                         float* __restrict__ out){
    __shared__ float hbuf[INNER];
    __shared__ float sh1[8], sh2[8];
    int t = blockIdx.x;
    int n = t & (SEQ-1);
    size_t base = (size_t)t * INNER2;
    float s = 0.f, s2 = 0.f;
    for (int c = threadIdx.x; c < INNER; c += blockDim.x){
        float w0 = cw[c*3+0], w1 = cw[c*3+1], w2 = cw[c*3+2];
        float a = ((n >= 2) ? g1[base - 2*(size_t)INNER2 + c] : 0.f) * w0
                + ((n >= 1) ? g1[base -   (size_t)INNER2 + c] : 0.f) * w1
                +              g1[base + c] * w2;
        int cg = c + INNER;
        float v0 = cw[cg*3+0], v1 = cw[cg*3+1], v2 = cw[cg*3+2];
        float g = ((n >= 2) ? g1[base - 2*(size_t)INNER2 + cg] : 0.f) * v0
                + ((n >= 1) ? g1[base -   (size_t)INNER2 + cg] : 0.f) * v1
                +              g1[base + cg] * v2;
        float gg = 0.5f * g * (1.f + erff(g * 0.70710678118654752f));
        float h = gg * a;
        hbuf[c] = h;
        s += h; s2 += h*h;
    }
    int lane = threadIdx.x & 31, warp = threadIdx.x >> 5;
    #pragma unroll
    for (int off = 16; off; off >>= 1){
        s  += __shfl_xor_sync(0xffffffffu, s,  off);
        s2 += __shfl_xor_sync(0xffffffffu, s2, off);
    }
    if (lane == 0){ sh1[warp] = s; sh2[warp] = s2; }
    __syncthreads();
    if (warp == 0){
        s  = (lane < 8) ? sh1[lane] : 0.f;
        s2 = (lane < 8) ? sh2[lane] : 0.f;
        #pragma unroll
        for (int off = 4; off; off >>= 1){
            s  += __shfl_xor_sync(0xffffffffu, s,  off);
            s2 += __shfl_xor_sync(0xffffffffu, s2, off);
        }
        if (lane == 0){ sh1[0] = s; sh2[0] = s2; }
    }
    __syncthreads();
    float m   = sh1[0] / (float)INNER;
    float var = sh2[0] / (float)INNER - m*m;
    float r   = rsqrtf(var + 1e-5f);
    for (int c = threadIdx.x; c < INNER; c += blockDim.x)
        out[(size_t)t*INNER_P + c] = (hbuf[c] - m) * r * lng[c];
    for (int c = INNER + threadIdx.x; c < INNER_P; c += blockDim.x)
        out[(size_t)t*INNER_P + c] = 0.f;
}

// ---------------- launch helpers ----------------
static inline void run_gemm(const float* A, const float* W, const float* R, float* C,
                            int M, int K, int N, int lda){
    dim3 grid((N + 127)/128, M/128);
    gemm_mma_kernel<<<grid, 256>>>(A, W, R, C, M, K, N, lda);
}
static inline void run_gemm_splitk(const float* A, const float* W, float* Cpart,
                                   const float* R, float* C,
                                   int M, int K, int KH, int N, int lda){
    dim3 grid((N + 127)/128, M/128, 2);
    gemm_mma_splitk_kernel<<<grid, 256>>>(A, W, Cpart, M, K, KH, N, lda);
    int n4 = (int)(((size_t)M*N) >> 2);
    combine_kernel<<<(n4 + 255)/256, 256>>>(Cpart, R, C, n4);
}

extern "C" void kernel_launch(void* const* d_in, const int* in_sizes, int n_in,
                              void* d_out, int out_size){
    const float* x     = (const float*)d_in[0];
    const float* rel   = (const float*)d_in[1];
    const float* qn_g  = (const float*)d_in[2];
    const float* wq    = (const float*)d_in[3];
    const float* wkv   = (const float*)d_in[4];
    const float* wo    = (const float*)d_in[5];
    const float* ln1g  = (const float*)d_in[6];
    const float* w1    = (const float*)d_in[7];
    const float* convw = (const float*)d_in[8];
    const float* ln2g  = (const float*)d_in[9];
    const float* w2    = (const float*)d_in[10];
    const float* fing  = (const float*)d_in[11];
    float* out = (float*)d_out;

    float *px, *ph, *pqkv, *po, *pg1, *ph3, *pwqkv, *ppart;
    cudaGetSymbolAddress((void**)&px,    g_x);
    cudaGetSymbolAddress((void**)&ph,    g_h);
    cudaGetSymbolAddress((void**)&pqkv,  g_qkv);
    cudaGetSymbolAddress((void**)&po,    g_o);
    cudaGetSymbolAddress((void**)&pg1,   g_g1);
    cudaGetSymbolAddress((void**)&ph3,   g_h3);
    cudaGetSymbolAddress((void**)&pwqkv, g_wqkv);
    cudaGetSymbolAddress((void**)&ppart, g_part);

    cudaFuncSetAttribute(attn_kernel, cudaFuncAttributeMaxDynamicSharedMemorySize, ATTN_SMEM);

    bias_kernel<<<(SEQ*HEADS + 255)/256, 256>>>(rel);
    scale_copy_kernel<<<(TOK*DIM + 255)/256, 256>>>(x, px, TOK*DIM);
    {
        size_t tot = (size_t)DEPTH*DIM*QKV_N;
        pack_qkv_kernel<<<(unsigned)((tot + 255)/256), 256>>>(wq, wkv, pwqkv);
    }

    for (int l = 0; l < DEPTH; l++){
        // attention block
        ln1024_kernel<<<TOK, 256>>>(px, qn_g + l*DIM, ph);
        run_gemm_splitk(ph, pwqkv + (size_t)l*DIM*QKV_N, ppart, nullptr, pqkv,
                        TOK, DIM, 512, QKV_N, DIM);
        dim3 agrid(SEQ/AT_ROWS, HEADS, BATCH);
        attn_kernel<<<agrid, 256, ATTN_SMEM>>>(pqkv, po);
        run_gemm_splitk(po, wo + (size_t)l*DIM*DIM, ppart, px, px,
                        TOK, DIM, 512, DIM, DIM);

        // conv-GLU MLP block
        ln1024_kernel<<<TOK, 256>>>(px, ln1g + l*DIM, ph);
        run_gemm(ph, w1 + (size_t)l*DIM*INNER2, nullptr, pg1, TOK, DIM, INNER2, DIM);
        convglu_ln_kernel<<<TOK, 256>>>(pg1, convw + (size_t)l*INNER2*3,
                                        ln2g + (size_t)l*INNER, ph3);
        run_gemm_splitk(ph3, w2 + (size_t)l*INNER*DIM, ppart, px, px,
                        TOK, INNER, 1376, DIM, INNER_P);
    }
    ln1024_kernel<<<TOK, 256>>>(px, fing, out);
}

// round 14
// speedup vs baseline: 1.5710x; 1.0273x over previous
#include <cuda_runtime.h>
#include <math.h>
#include <float.h>
#include <stdint.h>

#define DEPTH  6
#define DIM    1024
#define HEADS  16
#define DH     64
#define INNER  2730
#define INNER_P 2732
#define INNER2 5460
#define BATCH  2
#define SEQ    1024
#define TOK    (BATCH*SEQ)
#define NBUCK  32
#define QKV_N  1152   // 1024 q + 64 k + 64 v

// ---------------- scratch ----------------
__device__ float g_x  [TOK*DIM];
__device__ float g_h  [TOK*DIM];
__device__ float g_qkv[(size_t)TOK*QKV_N + 32];
__device__ float g_o  [TOK*DIM];
__device__ float g_g1 [(size_t)TOK*INNER2 + 32];
__device__ float g_h3 [(size_t)TOK*INNER_P + 32];
__device__ float g_bias[SEQ*HEADS];
__device__ float g_wqkv[(size_t)DEPTH*DIM*QKV_N];
__device__ float g_part[2*(size_t)TOK*QKV_N];

// ---------------- rel-pos bias ----------------
__global__ void bias_kernel(const float* __restrict__ rel_emb){
    int idx = blockIdx.x*blockDim.x + threadIdx.x;
    if (idx >= SEQ*HEADS) return;
    int delta = idx / HEADS;
    int h     = idx % HEADS;
    int bucket;
    if (delta < NBUCK/2) {
        bucket = delta;
    } else {
        float nf = (float)delta;
        int vl = (NBUCK/2) + (int)(logf(nf / (float)(NBUCK/2)) / logf(8.0f) * (float)(NBUCK/2));
        bucket = vl < (NBUCK-1) ? vl : (NBUCK-1);
    }
    g_bias[idx] = rel_emb[bucket*HEADS + h];
}

__global__ void scale_copy_kernel(const float* __restrict__ in, float* __restrict__ out, int n){
    int i = blockIdx.x*blockDim.x + threadIdx.x;
    if (i < n){ float v = in[i]; out[i] = v*0.1f + v*0.9f; }
}

// ---------------- pack wq|wkv into combined weight ----------------
__global__ void pack_qkv_kernel(const float* __restrict__ wq, const float* __restrict__ wkv,
                                float* __restrict__ wqkv){
    size_t i = (size_t)blockIdx.x*256 + threadIdx.x;
    if (i >= (size_t)DEPTH*DIM*QKV_N) return;
    int c = (int)(i % QKV_N);
    size_t rk = i / QKV_N;
    int k = (int)(rk % DIM);
    int l = (int)(rk / DIM);
    wqkv[i] = (c < DIM) ? wq[((size_t)l*DIM + k)*DIM + c]
                        : wkv[((size_t)l*DIM + k)*(2*DH) + (c - DIM)];
}

// ---------------- combine split-K partials: C = P0 + P1 (+R) ----------------
__global__ __launch_bounds__(256) void combine_kernel(const float* __restrict__ P,
                                                      const float* __restrict__ R,
                                                      float* __restrict__ C, int n4){
    int i = blockIdx.x*blockDim.x + threadIdx.x;
    if (i >= n4) return;
    const float4* P0 = reinterpret_cast<const float4*>(P);
    const float4* P1 = P0 + n4;
    float4 a = P0[i], b = P1[i];
    float4 v = make_float4(a.x+b.x, a.y+b.y, a.z+b.z, a.w+b.w);
    if (R){
        float4 r = reinterpret_cast<const float4*>(R)[i];
        v.x += r.x; v.y += r.y; v.z += r.z; v.w += r.w;
    }
    reinterpret_cast<float4*>(C)[i] = v;
}

// ---- fused: x = P0 + P1 + R (written to X) ; LN(x)*gain -> outLN  (D=1024) ----
__global__ __launch_bounds__(256) void combine_ln_kernel(const float* __restrict__ P,
                                                         const float* __restrict__ R,
                                                         float* __restrict__ X,
                                                         const float* __restrict__ gn,
                                                         float* __restrict__ outLN){
    int t = blockIdx.x;
    size_t base4 = (size_t)t * (DIM/4);
    const float4* P0 = reinterpret_cast<const float4*>(P) + base4;
    const float4* P1 = reinterpret_cast<const float4*>(P) + (size_t)TOK*(DIM/4) + base4;
    const float4* Rr = reinterpret_cast<const float4*>(R) + base4;
    float4 a = P0[threadIdx.x], b = P1[threadIdx.x], r = Rr[threadIdx.x];
    float4 v = make_float4(a.x+b.x+r.x, a.y+b.y+r.y, a.z+b.z+r.z, a.w+b.w+r.w);
    reinterpret_cast<float4*>(X)[base4 + threadIdx.x] = v;
    float s  = v.x + v.y + v.z + v.w;
    float s2 = v.x*v.x + v.y*v.y + v.z*v.z + v.w*v.w;
    __shared__ float sh1[8], sh2[8];
    int lane = threadIdx.x & 31, warp = threadIdx.x >> 5;
    #pragma unroll
    for (int off = 16; off; off >>= 1){
        s  += __shfl_xor_sync(0xffffffffu, s,  off);
        s2 += __shfl_xor_sync(0xffffffffu, s2, off);
    }
    if (lane == 0){ sh1[warp] = s; sh2[warp] = s2; }
    __syncthreads();
    if (warp == 0){
        s  = (lane < 8) ? sh1[lane] : 0.f;
        s2 = (lane < 8) ? sh2[lane] : 0.f;
        #pragma unroll
        for (int off = 4; off; off >>= 1){
            s  += __shfl_xor_sync(0xffffffffu, s,  off);
            s2 += __shfl_xor_sync(0xffffffffu, s2, off);
        }
        if (lane == 0){ sh1[0] = s; sh2[0] = s2; }
    }
    __syncthreads();
    float m   = sh1[0] / (float)DIM;
    float var = sh2[0] / (float)DIM - m*m;
    float rr  = rsqrtf(var + 1e-5f);
    float4 gv = reinterpret_cast<const float4*>(gn)[threadIdx.x];
    float4 o;
    o.x = (v.x - m) * rr * gv.x;
    o.y = (v.y - m) * rr * gv.y;
    o.z = (v.z - m) * rr * gv.z;
    o.w = (v.w - m) * rr * gv.w;
    reinterpret_cast<float4*>(outLN)[base4 + threadIdx.x] = o;
}

// ---------------- LayerNorm specialized D=1024, 256 threads, float4 ----------------
__global__ __launch_bounds__(256) void ln1024_kernel(const float* __restrict__ in,
                                                     const float* __restrict__ g,
                                                     float* __restrict__ out){
    int t = blockIdx.x;
    const float4* row4 = reinterpret_cast<const float4*>(in + (size_t)t*DIM);
    float4 v = row4[threadIdx.x];
    float s  = v.x + v.y + v.z + v.w;
    float s2 = v.x*v.x + v.y*v.y + v.z*v.z + v.w*v.w;
    __shared__ float sh1[8], sh2[8];
    int lane = threadIdx.x & 31, warp = threadIdx.x >> 5;
    #pragma unroll
    for (int off = 16; off; off >>= 1){
        s  += __shfl_xor_sync(0xffffffffu, s,  off);
        s2 += __shfl_xor_sync(0xffffffffu, s2, off);
    }
    if (lane == 0){ sh1[warp] = s; sh2[warp] = s2; }
    __syncthreads();
    if (warp == 0){
        s  = (lane < 8) ? sh1[lane] : 0.f;
        s2 = (lane < 8) ? sh2[lane] : 0.f;
        #pragma unroll
        for (int off = 4; off; off >>= 1){
            s  += __shfl_xor_sync(0xffffffffu, s,  off);
            s2 += __shfl_xor_sync(0xffffffffu, s2, off);
        }
        if (lane == 0){ sh1[0] = s; sh2[0] = s2; }
    }
    __syncthreads();
    float m   = sh1[0] / (float)DIM;
    float var = sh2[0] / (float)DIM - m*m;
    float r   = rsqrtf(var + 1e-5f);
    const float4* g4 = reinterpret_cast<const float4*>(g);
    float4 gv = g4[threadIdx.x];
    float4 o;
    o.x = (v.x - m) * r * gv.x;
    o.y = (v.y - m) * r * gv.y;
    o.z = (v.z - m) * r * gv.z;
    o.w = (v.w - m) * r * gv.w;
    reinterpret_cast<float4*>(out + (size_t)t*DIM)[threadIdx.x] = o;
}

// ---------------- tf32 helpers ----------------
__device__ __forceinline__ float to_tf32(float x){
    uint32_t u; asm("cvt.rna.tf32.f32 %0, %1;" : "=r"(u) : "f"(x));
    return __uint_as_float(u);
}
__device__ __forceinline__ void mma_tf32(float* d, const uint32_t* a, const uint32_t* b){
    asm volatile(
        "mma.sync.aligned.m16n8k8.row.col.f32.tf32.tf32.f32 "
        "{%0,%1,%2,%3}, {%4,%5,%6,%7}, {%8,%9}, {%0,%1,%2,%3};\n"
        : "+f"(d[0]), "+f"(d[1]), "+f"(d[2]), "+f"(d[3])
        : "r"(a[0]), "r"(a[1]), "r"(a[2]), "r"(a[3]), "r"(b[0]), "r"(b[1]));
}

// ================= GEMM core (128x128, KT=16, double-buffered) =================
__device__ __forceinline__ void gemm_mainloop(const float* __restrict__ A,
                                              const float* __restrict__ W,
                                              float As[2][2048], float Bs[2][2048],
                                              int bm, int bn, int t,
                                              int K0, int Kend, int N, int lda,
                                              float acc[4][4][4]){
    const int lane = t & 31;
    const int warp = t >> 5;
    const int wm = warp >> 2;
    const int wn = warp & 3;

    float a_reg[2][4];
    float b_reg[8];
    int a_row[2], a_col[2];
    #pragma unroll
    for (int v = 0; v < 2; v++){
        int id = 2*t + v;
        int al = id & 31, mt = (id >> 5) & 7, g = id >> 8;
        a_row[v] = bm + mt*16 + (al >> 2);
        a_col[v] = g*8 + (al & 3);
    }
    int b_col[4], b_k[4];
    #pragma unroll
    for (int u = 0; u < 4; u++){
        int vid = 4*t + u;
        int lb = vid & 31, nt = (vid >> 5) & 15, g = vid >> 9;
        b_col[u] = bn + nt*8 + (lb >> 2);
        b_k[u]   = g*8 + (lb & 3);
    }

    const int ntiles = (Kend - K0 + 15) / 16;

    auto load_tile = [&](int k0){
        #pragma unroll
        for (int v = 0; v < 2; v++){
            const float* p = A + (size_t)a_row[v]*lda + k0 + a_col[v];
            a_reg[v][0] = p[0];
            a_reg[v][1] = p[(size_t)8*lda];
            a_reg[v][2] = p[4];
            a_reg[v][3] = p[(size_t)8*lda + 4];
        }
        #pragma unroll
        for (int u = 0; u < 4; u++){
            int kg = k0 + b_k[u];
            int cb = b_col[u];
            bool okc = (cb < N);
            b_reg[u*2+0] = (okc && kg     < Kend) ? W[(size_t)kg*N + cb]     : 0.f;
            b_reg[u*2+1] = (okc && kg + 4 < Kend) ? W[(size_t)(kg+4)*N + cb] : 0.f;
        }
    };
    auto store_tile = [&](int buf){
        #pragma unroll
        for (int v = 0; v < 2; v++){
            float4 q = make_float4(to_tf32(a_reg[v][0]), to_tf32(a_reg[v][1]),
                                   to_tf32(a_reg[v][2]), to_tf32(a_reg[v][3]));
            *reinterpret_cast<float4*>(&As[buf][(2*t + v)*4]) = q;
        }
        float4 q0 = make_float4(to_tf32(b_reg[0]), to_tf32(b_reg[1]),
                                to_tf32(b_reg[2]), to_tf32(b_reg[3]));
        float4 q1 = make_float4(to_tf32(b_reg[4]), to_tf32(b_reg[5]),
                                to_tf32(b_reg[6]), to_tf32(b_reg[7]));
        *reinterpret_cast<float4*>(&Bs[buf][8*t])     = q0;
        *reinterpret_cast<float4*>(&Bs[buf][8*t + 4]) = q1;
    };

    load_tile(K0);
    store_tile(0);
    __syncthreads();

    int buf = 0;
    for (int tile = 0; tile < ntiles; tile++){
        const bool more = (tile + 1 < ntiles);
        if (more) load_tile(K0 + (tile + 1) * 16);

        #pragma unroll
        for (int g = 0; g < 2; g++){
            uint32_t afr[4][4], bfr[4][2];
            #pragma unroll
            for (int i = 0; i < 4; i++)
                *reinterpret_cast<float4*>(afr[i]) =
                    *reinterpret_cast<const float4*>(&As[buf][((g*8 + wm*4 + i)*32 + lane)*4]);
            #pragma unroll
            for (int jn = 0; jn < 4; jn++)
                *reinterpret_cast<float2*>(bfr[jn]) =
                    *reinterpret_cast<const float2*>(&Bs[buf][((g*16 + wn*4 + jn)*32 + lane)*2]);
            #pragma unroll
            for (int i = 0; i < 4; i++)
                #pragma unroll
                for (int jn = 0; jn < 4; jn++)
                    mma_tf32(acc[i][jn], afr[i], bfr[jn]);
        }

        if (more) store_tile(buf ^ 1);
        __syncthreads();
        buf ^= 1;
    }
}

__device__ __forceinline__ void gemm_epilogue(float* __restrict__ C,
                                              const float* __restrict__ R,
                                              int bm, int bn, int t, int N,
                                              float acc[4][4][4]){
    const int lane = t & 31;
    const int warp = t >> 5;
    const int wm = warp >> 2;
    const int wn = warp & 3;
    const int r0 = bm + wm*64 + (lane >> 2);
    const int c0 = bn + wn*32 + (lane & 3)*2;
    #pragma unroll
    for (int i = 0; i < 4; i++){
        #pragma unroll
        for (int jn = 0; jn < 4; jn++){
            int col = c0 + jn*8;
            #pragma unroll
            for (int half = 0; half < 2; half++){
                int row = r0 + i*16 + half*8;
                size_t base = (size_t)row * N;
                float v0 = acc[i][jn][half*2 + 0];
                float v1 = acc[i][jn][half*2 + 1];
                if (col + 1 < N){
                    if (R){ v0 += R[base + col]; v1 += R[base + col + 1]; }
                    C[base + col]     = v0;
                    C[base + col + 1] = v1;
                } else if (col < N){
                    if (R) v0 += R[base + col];
                    C[base + col] = v0;
                }
            }
        }
    }
}

// ---------------- plain GEMM ----------------
__global__ __launch_bounds__(256, 2) void gemm_mma_kernel(const float* __restrict__ A,
                                                          const float* __restrict__ W,
                                                          const float* __restrict__ R,
                                                          float* __restrict__ C,
                                                          int M, int K, int N, int lda){
    __shared__ float As[2][2048];
    __shared__ float Bs[2][2048];
    const int bm = blockIdx.y * 128;
    const int bn = blockIdx.x * 128;
    const int t  = threadIdx.x;
    float acc[4][4][4];
    #pragma unroll
    for (int i = 0; i < 4; i++)
        #pragma unroll
        for (int j = 0; j < 4; j++)
            #pragma unroll
            for (int q = 0; q < 4; q++) acc[i][j][q] = 0.f;
    gemm_mainloop(A, W, As, Bs, bm, bn, t, 0, K, N, lda, acc);
    gemm_epilogue(C, R, bm, bn, t, N, acc);
}

// ---------------- split-K GEMM ----------------
__global__ __launch_bounds__(256, 2) void gemm_mma_splitk_kernel(const float* __restrict__ A,
                                                                 const float* __restrict__ W,
                                                                 float* __restrict__ Cpart,
                                                                 int M, int K, int KH,
                                                                 int N, int lda){
    __shared__ float As[2][2048];
    __shared__ float Bs[2][2048];
    const int bm = blockIdx.y * 128;
    const int bn = blockIdx.x * 128;
    const int t  = threadIdx.x;
    const int z  = blockIdx.z;
    const int K0   = z * KH;
    const int Kend = (K0 + KH < K) ? (K0 + KH) : K;
    float acc[4][4][4];
    #pragma unroll
    for (int i = 0; i < 4; i++)
        #pragma unroll
        for (int j = 0; j < 4; j++)
            #pragma unroll
            for (int q = 0; q < 4; q++) acc[i][j][q] = 0.f;
    gemm_mainloop(A, W, As, Bs, bm, bn, t, K0, Kend, N, lda, acc);
    gemm_epilogue(Cpart + (size_t)z*M*N, nullptr, bm, bn, t, N, acc);
}

// ---------------- fused attention: 32 rows/block, reg-Q, single-exp softmax ----------------
#define AT_ROWS 32
#define KV_LD 68
#define ATTN_SMEM ((AT_ROWS*SEQ + 2*64*KV_LD + 32) * (int)sizeof(float))

__global__ __launch_bounds__(512) void attn_kernel(const float* __restrict__ qkv,
                                                   float* __restrict__ o){
    extern __shared__ float sm[];
    float* S    = sm;                     // 32 x SEQ (unnormalized p after softmax pass)
    float* Ks   = S  + AT_ROWS*SEQ;       // 64 x KV_LD
    float* Vs   = Ks + 64*KV_LD;          // 64 x KV_LD
    float* Sinv = Vs + 64*KV_LD;          // 32 row inverses
    int it = blockIdx.x;
    int h  = blockIdx.y;
    int b  = blockIdx.z;
    int i0 = it * AT_ROWS;
    int tid = threadIdx.x;
    int row = tid >> 4;                   // 0..31
    int q16 = tid & 15;
    int i   = i0 + row;

    float4 qreg[16];
    {
        const float4* qp = reinterpret_cast<const float4*>(
            qkv + (size_t)(b*SEQ + i)*QKV_N + h*DH);
        #pragma unroll
        for (int c = 0; c < 16; c++){
            float4 v = qp[c];
            v.x *= 0.125f; v.y *= 0.125f; v.z *= 0.125f; v.w *= 0.125f;
            qreg[c] = v;
        }
    }

    int njt = (i0 + AT_ROWS - 1)/64 + 1;

    // ---- scores ----
    for (int jt = 0; jt < njt; jt++){
        for (int idx = tid; idx < 64*16; idx += 512){
            int r = idx >> 4, c4 = idx & 15;
            float4 v = *reinterpret_cast<const float4*>(
                qkv + (size_t)(b*SEQ + jt*64 + r)*QKV_N + DIM + c4*4);
            *reinterpret_cast<float4*>(&Ks[r*KV_LD + c4*4]) = v;
        }
        __syncthreads();
        #pragma unroll
        for (int jj = 0; jj < 4; jj++){
            int jl = jj*16 + q16;
            int j  = jt*64 + jl;
            float acc = 0.f;
            #pragma unroll
            for (int c = 0; c < 16; c++){
                float4 k4 = *reinterpret_cast<const float4*>(&Ks[jl*KV_LD + c*4]);
                acc += qreg[c].x*k4.x + qreg[c].y*k4.y + qreg[c].z*k4.z + qreg[c].w*k4.w;
            }
            S[row*SEQ + j] = (j <= i) ? (acc + g_bias[(i-j)*HEADS + h]) : -FLT_MAX;
        }
        __syncthreads();
    }

    // ---- softmax pass: p = exp(S-mx) stored unnormalized; 1/sum per row ----
    int warp = tid >> 5, lane = tid & 31;
    int ncol = njt * 64;
    for (int r = warp*2; r < warp*2 + 2; r++){
        int ii = i0 + r;
        float mx = -FLT_MAX;
        for (int j = lane; j <= ii; j += 32) mx = fmaxf(mx, S[r*SEQ + j]);
        #pragma unroll
        for (int off = 16; off; off >>= 1) mx = fmaxf(mx, __shfl_xor_sync(0xffffffffu, mx, off));
        float sum = 0.f;
        for (int j = lane; j < ncol; j += 32){
            float p = __expf(S[r*SEQ + j] - mx);   // masked cells (-FLT_MAX) -> 0
            S[r*SEQ + j] = p;
            sum += p;
        }
        #pragma unroll
        for (int off = 16; off; off >>= 1) sum += __shfl_xor_sync(0xffffffffu, sum, off);
        if (lane == 0) Sinv[r] = __frcp_rn(sum);
    }
    __syncthreads();

    // ---- attn @ V with float4 S loads; normalize at the end ----
    float4 accv = make_float4(0.f, 0.f, 0.f, 0.f);
    for (int jt = 0; jt < njt; jt++){
        for (int idx = tid; idx < 64*16; idx += 512){
            int r = idx >> 4, c4 = idx & 15;
            float4 v = *reinterpret_cast<const float4*>(
                qkv + (size_t)(b*SEQ + jt*64 + r)*QKV_N + DIM + DH + c4*4);
            *reinterpret_cast<float4*>(&Vs[r*KV_LD + c4*4]) = v;
        }
        __syncthreads();
        #pragma unroll 4
        for (int j4 = 0; j4 < 16; j4++){
            float4 s4 = *reinterpret_cast<const float4*>(&S[row*SEQ + jt*64 + j4*4]);
            float4 v0 = *reinterpret_cast<const float4*>(&Vs[(j4*4+0)*KV_LD + q16*4]);
            float4 v1 = *reinterpret_cast<const float4*>(&Vs[(j4*4+1)*KV_LD + q16*4]);
            float4 v2 = *reinterpret_cast<const float4*>(&Vs[(j4*4+2)*KV_LD + q16*4]);
            float4 v3 = *reinterpret_cast<const float4*>(&Vs[(j4*4+3)*KV_LD + q16*4]);
            accv.x += s4.x*v0.x + s4.y*v1.x + s4.z*v2.x + s4.w*v3.x;
            accv.y += s4.x*v0.y + s4.y*v1.y + s4.z*v2.y + s4.w*v3.y;
            accv.z += s4.x*v0.z + s4.y*v1.z + s4.z*v2.z + s4.w*v3.z;
            accv.w += s4.x*v0.w + s4.y*v1.w + s4.z*v2.w + s4.w*v3.w;
        }
        __syncthreads();
    }
    float inv = Sinv[row];
    accv.x *= inv; accv.y *= inv; accv.z *= inv; accv.w *= inv;
    *reinterpret_cast<float4*>(o + (size_t)(b*SEQ + i)*DIM + h*DH + q16*4) = accv;
}

// ---------------- fused causal conv(3) + GELU-GLU + LayerNorm ----------------
__global__ __launch_bounds__(256) void convglu_ln_kernel(const float* __restrict__ g1,
                                                         const float* __restrict__ cw,
                                                         const float* __restrict__ lng,
                                                         float* __restrict__ out){
    __shared__ float hbuf[INNER];
    __shared__ float sh1[8], sh2[8];
    int t = blockIdx.x;
    int n = t & (SEQ-1);
    size_t base = (size_t)t * INNER2;
    float s = 0.f, s2 = 0.f;
    for (int c = threadIdx.x; c < INNER; c += blockDim.x){
        float w0 = cw[c*3+0], w1 = cw[c*3+1], w2 = cw[c*3+2];
        float a = ((n >= 2) ? g1[base - 2*(size_t)INNER2 + c] : 0.f) * w0
                + ((n >= 1) ? g1[base -   (size_t)INNER2 + c] : 0.f) * w1
                +              g1[base + c] * w2;
        int cg = c + INNER;
        float v0 = cw[cg*3+0], v1 = cw[cg*3+1], v2 = cw[cg*3+2];
        float g = ((n >= 2) ? g1[base - 2*(size_t)INNER2 + cg] : 0.f) * v0
                + ((n >= 1) ? g1[base -   (size_t)INNER2 + cg] : 0.f) * v1
                +              g1[base + cg] * v2;
        float gg = 0.5f * g * (1.f + erff(g * 0.70710678118654752f));
        float h = gg * a;
        hbuf[c] = h;
        s += h; s2 += h*h;
    }
    int lane = threadIdx.x & 31, warp = threadIdx.x >> 5;
    #pragma unroll
    for (int off = 16; off; off >>= 1){
        s  += __shfl_xor_sync(0xffffffffu, s,  off);
        s2 += __shfl_xor_sync(0xffffffffu, s2, off);
    }
    if (lane == 0){ sh1[warp] = s; sh2[warp] = s2; }
    __syncthreads();
    if (warp == 0){
        s  = (lane < 8) ? sh1[lane] : 0.f;
        s2 = (lane < 8) ? sh2[lane] : 0.f;
        #pragma unroll
        for (int off = 4; off; off >>= 1){
            s  += __shfl_xor_sync(0xffffffffu, s,  off);
            s2 += __shfl_xor_sync(0xffffffffu, s2, off);
        }
        if (lane == 0){ sh1[0] = s; sh2[0] = s2; }
    }
    __syncthreads();
    float m   = sh1[0] / (float)INNER;
    float var = sh2[0] / (float)INNER - m*m;
    float r   = rsqrtf(var + 1e-5f);
    for (int c = threadIdx.x; c < INNER; c += blockDim.x)
        out[(size_t)t*INNER_P + c] = (hbuf[c] - m) * r * lng[c];
    for (int c = INNER + threadIdx.x; c < INNER_P; c += blockDim.x)
        out[(size_t)t*INNER_P + c] = 0.f;
}

// ---------------- launch helpers ----------------
static inline void run_gemm(const float* A, const float* W, const float* R, float* C,
                            int M, int K, int N, int lda){
    dim3 grid((N + 127)/128, M/128);
    gemm_mma_kernel<<<grid, 256>>>(A, W, R, C, M, K, N, lda);
}
static inline void run_gemm_splitk_raw(const float* A, const float* W, float* Cpart,
                                       int M, int K, int KH, int N, int lda){
    dim3 grid((N + 127)/128, M/128, 2);
    gemm_mma_splitk_kernel<<<grid, 256>>>(A, W, Cpart, M, K, KH, N, lda);
}

extern "C" void kernel_launch(void* const* d_in, const int* in_sizes, int n_in,
                              void* d_out, int out_size){
    const float* x     = (const float*)d_in[0];
    const float* rel   = (const float*)d_in[1];
    const float* qn_g  = (const float*)d_in[2];
    const float* wq    = (const float*)d_in[3];
    const float* wkv   = (const float*)d_in[4];
    const float* wo    = (const float*)d_in[5];
    const float* ln1g  = (const float*)d_in[6];
    const float* w1    = (const float*)d_in[7];
    const float* convw = (const float*)d_in[8];
    const float* ln2g  = (const float*)d_in[9];
    const float* w2    = (const float*)d_in[10];
    const float* fing  = (const float*)d_in[11];
    float* out = (float*)d_out;

    float *px, *ph, *pqkv, *po, *pg1, *ph3, *pwqkv, *ppart;
    cudaGetSymbolAddress((void**)&px,    g_x);
    cudaGetSymbolAddress((void**)&ph,    g_h);
    cudaGetSymbolAddress((void**)&pqkv,  g_qkv);
    cudaGetSymbolAddress((void**)&po,    g_o);
    cudaGetSymbolAddress((void**)&pg1,   g_g1);
    cudaGetSymbolAddress((void**)&ph3,   g_h3);
    cudaGetSymbolAddress((void**)&pwqkv, g_wqkv);
    cudaGetSymbolAddress((void**)&ppart, g_part);

    cudaFuncSetAttribute(attn_kernel, cudaFuncAttributeMaxDynamicSharedMemorySize, ATTN_SMEM);

    bias_kernel<<<(SEQ*HEADS + 255)/256, 256>>>(rel);
    scale_copy_kernel<<<(TOK*DIM + 255)/256, 256>>>(x, px, TOK*DIM);
    {
        size_t tot = (size_t)DEPTH*DIM*QKV_N;
        pack_qkv_kernel<<<(unsigned)((tot + 255)/256), 256>>>(wq, wkv, pwqkv);
    }

    // first LN (layer 0 qn)
    ln1024_kernel<<<TOK, 256>>>(px, qn_g, ph);

    for (int l = 0; l < DEPTH; l++){
        // attention block
        run_gemm_splitk_raw(ph, pwqkv + (size_t)l*DIM*QKV_N, ppart, TOK, DIM, 512, QKV_N, DIM);
        {
            int n4 = (int)(((size_t)TOK*QKV_N) >> 2);
            combine_kernel<<<(n4 + 255)/256, 256>>>(ppart, nullptr, pqkv, n4);
        }
        dim3 agrid(SEQ/AT_ROWS, HEADS, BATCH);
        attn_kernel<<<agrid, 512, ATTN_SMEM>>>(pqkv, po);
        // wo GEMM -> fused combine(+residual) + LN(ln1g) -> px, ph
        run_gemm_splitk_raw(po, wo + (size_t)l*DIM*DIM, ppart, TOK, DIM, 512, DIM, DIM);
        combine_ln_kernel<<<TOK, 256>>>(ppart, px, px, ln1g + l*DIM, ph);

        // conv-GLU MLP block
        run_gemm(ph, w1 + (size_t)l*DIM*INNER2, nullptr, pg1, TOK, DIM, INNER2, DIM);
        convglu_ln_kernel<<<TOK, 256>>>(pg1, convw + (size_t)l*INNER2*3,
                                        ln2g + (size_t)l*INNER, ph3);
        // w2 GEMM -> fused combine(+residual) + LN(next qn / final) -> px, (ph or out)
        run_gemm_splitk_raw(ph3, w2 + (size_t)l*INNER*DIM, ppart, TOK, INNER, 1376, DIM, INNER_P);
        if (l + 1 < DEPTH){
            combine_ln_kernel<<<TOK, 256>>>(ppart, px, px, qn_g + (l+1)*DIM, ph);
        } else {
            combine_ln_kernel<<<TOK, 256>>>(ppart, px, px, fing, out);
        }
    }
}

// round 17
// speedup vs baseline: 1.9970x; 1.2712x over previous
#include <cuda_runtime.h>
#include <cuda_bf16.h>
#include <math.h>
#include <float.h>
#include <stdint.h>

#define DEPTH  6
#define DIM    1024
#define HEADS  16
#define DH     64
#define INNER  2730
#define INNER_P 2732
#define INNER2 5460
#define BATCH  2
#define SEQ    1024
#define TOK    (BATCH*SEQ)
#define NBUCK  32
#define QKV_N  1152   // 1024 q + 64 k + 64 v

// ---------------- scratch ----------------
__device__ float g_x  [TOK*DIM];
__device__ float g_h  [TOK*DIM];
__device__ float g_qkv[(size_t)TOK*QKV_N + 32];
__device__ float g_o  [TOK*DIM];
__device__ float g_g1 [(size_t)TOK*INNER2 + 32];
__device__ float g_h3 [(size_t)TOK*INNER_P + 64];
__device__ float g_bias[SEQ*HEADS];
__device__ float g_wqkv[(size_t)DEPTH*DIM*QKV_N];
__device__ float g_part[2*(size_t)TOK*QKV_N];

// ---------------- rel-pos bias ----------------
__global__ void bias_kernel(const float* __restrict__ rel_emb){
    int idx = blockIdx.x*blockDim.x + threadIdx.x;
    if (idx >= SEQ*HEADS) return;
    int delta = idx / HEADS;
    int h     = idx % HEADS;
    int bucket;
    if (delta < NBUCK/2) {
        bucket = delta;
    } else {
        float nf = (float)delta;
        int vl = (NBUCK/2) + (int)(logf(nf / (float)(NBUCK/2)) / logf(8.0f) * (float)(NBUCK/2));
        bucket = vl < (NBUCK-1) ? vl : (NBUCK-1);
    }
    g_bias[idx] = rel_emb[bucket*HEADS + h];
}

__global__ void scale_copy_kernel(const float* __restrict__ in, float* __restrict__ out, int n){
    int i = blockIdx.x*blockDim.x + threadIdx.x;
    if (i < n){ float v = in[i]; out[i] = v*0.1f + v*0.9f; }
}

// ---------------- pack wq|wkv into combined weight ----------------
__global__ void pack_qkv_kernel(const float* __restrict__ wq, const float* __restrict__ wkv,
                                float* __restrict__ wqkv){
    size_t i = (size_t)blockIdx.x*256 + threadIdx.x;
    if (i >= (size_t)DEPTH*DIM*QKV_N) return;
    int c = (int)(i % QKV_N);
    size_t rk = i / QKV_N;
    int k = (int)(rk % DIM);
    int l = (int)(rk / DIM);
    wqkv[i] = (c < DIM) ? wq[((size_t)l*DIM + k)*DIM + c]
                        : wkv[((size_t)l*DIM + k)*(2*DH) + (c - DIM)];
}

// ---------------- combine split-K partials: C = P0 + P1 (+R) ----------------
__global__ __launch_bounds__(256) void combine_kernel(const float* __restrict__ P,
                                                      const float* __restrict__ R,
                                                      float* __restrict__ C, int n4){
    int i = blockIdx.x*blockDim.x + threadIdx.x;
    if (i >= n4) return;
    const float4* P0 = reinterpret_cast<const float4*>(P);
    const float4* P1 = P0 + n4;
    float4 a = P0[i], b = P1[i];
    float4 v = make_float4(a.x+b.x, a.y+b.y, a.z+b.z, a.w+b.w);
    if (R){
        float4 r = reinterpret_cast<const float4*>(R)[i];
        v.x += r.x; v.y += r.y; v.z += r.z; v.w += r.w;
    }
    reinterpret_cast<float4*>(C)[i] = v;
}

// ---- fused: x = P0 + P1 + R (written to X) ; LN(x)*gain -> outLN  (D=1024) ----
__global__ __launch_bounds__(256) void combine_ln_kernel(const float* __restrict__ P,
                                                         const float* __restrict__ R,
                                                         float* __restrict__ X,
                                                         const float* __restrict__ gn,
                                                         float* __restrict__ outLN){
    int t = blockIdx.x;
    size_t base4 = (size_t)t * (DIM/4);
    const float4* P0 = reinterpret_cast<const float4*>(P) + base4;
    const float4* P1 = reinterpret_cast<const float4*>(P) + (size_t)TOK*(DIM/4) + base4;
    const float4* Rr = reinterpret_cast<const float4*>(R) + base4;
    float4 a = P0[threadIdx.x], b = P1[threadIdx.x], r = Rr[threadIdx.x];
    float4 v = make_float4(a.x+b.x+r.x, a.y+b.y+r.y, a.z+b.z+r.z, a.w+b.w+r.w);
    reinterpret_cast<float4*>(X)[base4 + threadIdx.x] = v;
    float s  = v.x + v.y + v.z + v.w;
    float s2 = v.x*v.x + v.y*v.y + v.z*v.z + v.w*v.w;
    __shared__ float sh1[8], sh2[8];
    int lane = threadIdx.x & 31, warp = threadIdx.x >> 5;
    #pragma unroll
    for (int off = 16; off; off >>= 1){
        s  += __shfl_xor_sync(0xffffffffu, s,  off);
        s2 += __shfl_xor_sync(0xffffffffu, s2, off);
    }
    if (lane == 0){ sh1[warp] = s; sh2[warp] = s2; }
    __syncthreads();
    if (warp == 0){
        s  = (lane < 8) ? sh1[lane] : 0.f;
        s2 = (lane < 8) ? sh2[lane] : 0.f;
        #pragma unroll
        for (int off = 4; off; off >>= 1){
            s  += __shfl_xor_sync(0xffffffffu, s,  off);
            s2 += __shfl_xor_sync(0xffffffffu, s2, off);
        }
        if (lane == 0){ sh1[0] = s; sh2[0] = s2; }
    }
    __syncthreads();
    float m   = sh1[0] / (float)DIM;
    float var = sh2[0] / (float)DIM - m*m;
    float rr  = rsqrtf(var + 1e-5f);
    float4 gv = reinterpret_cast<const float4*>(gn)[threadIdx.x];
    float4 o;
    o.x = (v.x - m) * rr * gv.x;
    o.y = (v.y - m) * rr * gv.y;
    o.z = (v.z - m) * rr * gv.z;
    o.w = (v.w - m) * rr * gv.w;
    reinterpret_cast<float4*>(outLN)[base4 + threadIdx.x] = o;
}

// ---------------- LayerNorm specialized D=1024, 256 threads, float4 ----------------
__global__ __launch_bounds__(256) void ln1024_kernel(const float* __restrict__ in,
                                                     const float* __restrict__ g,
                                                     float* __restrict__ out){
    int t = blockIdx.x;
    const float4* row4 = reinterpret_cast<const float4*>(in + (size_t)t*DIM);
    float4 v = row4[threadIdx.x];
    float s  = v.x + v.y + v.z + v.w;
    float s2 = v.x*v.x + v.y*v.y + v.z*v.z + v.w*v.w;
    __shared__ float sh1[8], sh2[8];
    int lane = threadIdx.x & 31, warp = threadIdx.x >> 5;
    #pragma unroll
    for (int off = 16; off; off >>= 1){
        s  += __shfl_xor_sync(0xffffffffu, s,  off);
        s2 += __shfl_xor_sync(0xffffffffu, s2, off);
    }
    if (lane == 0){ sh1[warp] = s; sh2[warp] = s2; }
    __syncthreads();
    if (warp == 0){
        s  = (lane < 8) ? sh1[lane] : 0.f;
        s2 = (lane < 8) ? sh2[lane] : 0.f;
        #pragma unroll
        for (int off = 4; off; off >>= 1){
            s  += __shfl_xor_sync(0xffffffffu, s,  off);
            s2 += __shfl_xor_sync(0xffffffffu, s2, off);
        }
        if (lane == 0){ sh1[0] = s; sh2[0] = s2; }
    }
    __syncthreads();
    float m   = sh1[0] / (float)DIM;
    float var = sh2[0] / (float)DIM - m*m;
    float r   = rsqrtf(var + 1e-5f);
    const float4* g4 = reinterpret_cast<const float4*>(g);
    float4 gv = g4[threadIdx.x];
    float4 o;
    o.x = (v.x - m) * r * gv.x;
    o.y = (v.y - m) * r * gv.y;
    o.z = (v.z - m) * r * gv.z;
    o.w = (v.w - m) * r * gv.w;
    reinterpret_cast<float4*>(out + (size_t)t*DIM)[threadIdx.x] = o;
}

// ---------------- bf16 helpers ----------------
__device__ __forceinline__ uint32_t pbf(float lo, float hi){
    __nv_bfloat162 v = __floats2bfloat162_rn(lo, hi);
    return *reinterpret_cast<uint32_t*>(&v);
}
__device__ __forceinline__ void mma_bf16(float* d, const uint32_t* a, const uint32_t* b){
    asm volatile(
        "mma.sync.aligned.m16n8k16.row.col.f32.bf16.bf16.f32 "
        "{%0,%1,%2,%3}, {%4,%5,%6,%7}, {%8,%9}, {%0,%1,%2,%3};\n"
        : "+f"(d[0]), "+f"(d[1]), "+f"(d[2]), "+f"(d[3])
        : "r"(a[0]), "r"(a[1]), "r"(a[2]), "r"(a[3]), "r"(b[0]), "r"(b[1]));
}

// ================= bf16 GEMM core (128x128, KT=32, double-buffered) =================
// Fragment-permuted smem staging:
//  As[buf]: 512 fragment-vectors (4 x uint32 = one m16n8k16 A frag): id = (ks*8+mt)*32+lane
//  Bs[buf]: 1024 fragment-pairs (2 x uint32 = one B frag): vid = (ks*16+nt)*32+lane
// A rows must be readable to K0+KT-1 (+pads provided); B guarded per element.
__device__ __forceinline__ void gemm_mainloop(const float* __restrict__ A,
                                              const float* __restrict__ W,
                                              uint32_t As[2][2048], uint32_t Bs[2][2048],
                                              int bm, int bn, int t,
                                              int K0, int Kend, int N, int lda,
                                              float acc[4][4][4]){
    const int lane = t & 31;
    const int warp = t >> 5;
    const int wm = warp >> 2;          // 0..1 (64 rows)
    const int wn = warp & 3;           // 0..3 (32 cols)

    // staging coordinates
    int a_row[2], a_c0[2];
    #pragma unroll
    for (int v = 0; v < 2; v++){
        int id = 2*t + v;
        int al = id & 31, mt = (id >> 5) & 7, ks = id >> 8;
        a_row[v] = bm + mt*16 + (al >> 2);
        a_c0[v]  = (al & 3)*2 + ks*16;
    }
    int b_col[4], b_k0[4];
    #pragma unroll
    for (int u = 0; u < 4; u++){
        int vid = 4*t + u;
        int lb = vid & 31, nt = (vid >> 5) & 15, ks = vid >> 9;
        b_col[u] = bn + nt*8 + (lb >> 2);
        b_k0[u]  = (lb & 3)*2 + ks*16;
    }

    const int ntiles = (Kend - K0 + 31) / 32;

    float2 a_lo0[2], a_lo1[2], a_hi0[2], a_hi1[2];
    float  b_e[4][4];

    auto load_tile = [&](int k0){
        #pragma unroll
        for (int v = 0; v < 2; v++){
            const float* p = A + (size_t)a_row[v]*lda + k0 + a_c0[v];
            a_lo0[v] = *reinterpret_cast<const float2*>(p);
            a_lo1[v] = *reinterpret_cast<const float2*>(p + (size_t)8*lda);
            a_hi0[v] = *reinterpret_cast<const float2*>(p + 8);
            a_hi1[v] = *reinterpret_cast<const float2*>(p + (size_t)8*lda + 8);
        }
        #pragma unroll
        for (int u = 0; u < 4; u++){
            int kg = k0 + b_k0[u];
            int cb = b_col[u];
            bool okc = (cb < N);
            b_e[u][0] = (okc && kg     < Kend) ? W[(size_t)(kg  )*N + cb] : 0.f;
            b_e[u][1] = (okc && kg + 1 < Kend) ? W[(size_t)(kg+1)*N + cb] : 0.f;
            b_e[u][2] = (okc && kg + 8 < Kend) ? W[(size_t)(kg+8)*N + cb] : 0.f;
            b_e[u][3] = (okc && kg + 9 < Kend) ? W[(size_t)(kg+9)*N + cb] : 0.f;
        }
    };
    auto store_tile = [&](int buf){
        #pragma unroll
        for (int v = 0; v < 2; v++){
            uint4 q;
            q.x = pbf(a_lo0[v].x, a_lo0[v].y);
            q.y = pbf(a_lo1[v].x, a_lo1[v].y);
            q.z = pbf(a_hi0[v].x, a_hi0[v].y);
            q.w = pbf(a_hi1[v].x, a_hi1[v].y);
            *reinterpret_cast<uint4*>(&As[buf][(2*t + v)*4]) = q;
        }
        uint4 q0, q1;
        q0.x = pbf(b_e[0][0], b_e[0][1]); q0.y = pbf(b_e[0][2], b_e[0][3]);
        q0.z = pbf(b_e[1][0], b_e[1][1]); q0.w = pbf(b_e[1][2], b_e[1][3]);
        q1.x = pbf(b_e[2][0], b_e[2][1]); q1.y = pbf(b_e[2][2], b_e[2][3]);
        q1.z = pbf(b_e[3][0], b_e[3][1]); q1.w = pbf(b_e[3][2], b_e[3][3]);
        *reinterpret_cast<uint4*>(&Bs[buf][8*t])     = q0;
        *reinterpret_cast<uint4*>(&Bs[buf][8*t + 4]) = q1;
    };

    load_tile(K0);
    store_tile(0);
    __syncthreads();

    int buf = 0;
    for (int tile = 0; tile < ntiles; tile++){
        const bool more = (tile + 1 < ntiles);
        if (more) load_tile(K0 + (tile + 1) * 32);

        #pragma unroll
        for (int ks = 0; ks < 2; ks++){
            uint32_t afr[4][4], bfr[4][2];
            #pragma unroll
            for (int i = 0; i < 4; i++)
                *reinterpret_cast<uint4*>(afr[i]) =
                    *reinterpret_cast<const uint4*>(&As[buf][((ks*8 + wm*4 + i)*32 + lane)*4]);
            #pragma unroll
            for (int jn = 0; jn < 4; jn++)
                *reinterpret_cast<uint2*>(bfr[jn]) =
                    *reinterpret_cast<const uint2*>(&Bs[buf][((ks*16 + wn*4 + jn)*32 + lane)*2]);
            #pragma unroll
            for (int i = 0; i < 4; i++)
                #pragma unroll
                for (int jn = 0; jn < 4; jn++)
                    mma_bf16(acc[i][jn], afr[i], bfr[jn]);
        }

        if (more) store_tile(buf ^ 1);
        __syncthreads();
        buf ^= 1;
    }
}

__device__ __forceinline__ void gemm_epilogue(float* __restrict__ C,
                                              const float* __restrict__ R,
                                              int bm, int bn, int t, int N,
                                              float acc[4][4][4]){
    const int lane = t & 31;
    const int warp = t >> 5;
    const int wm = warp >> 2;
    const int wn = warp & 3;
    const int r0 = bm + wm*64 + (lane >> 2);
    const int c0 = bn + wn*32 + (lane & 3)*2;
    #pragma unroll
    for (int i = 0; i < 4; i++){
        #pragma unroll
        for (int jn = 0; jn < 4; jn++){
            int col = c0 + jn*8;
            #pragma unroll
            for (int half = 0; half < 2; half++){
                int row = r0 + i*16 + half*8;
                size_t base = (size_t)row * N;
                float v0 = acc[i][jn][half*2 + 0];
                float v1 = acc[i][jn][half*2 + 1];
                if (col + 1 < N){
                    if (R){ v0 += R[base + col]; v1 += R[base + col + 1]; }
                    C[base + col]     = v0;
                    C[base + col + 1] = v1;
                } else if (col < N){
                    if (R) v0 += R[base + col];
                    C[base + col] = v0;
                }
            }
        }
    }
}

// ---------------- plain GEMM ----------------
__global__ __launch_bounds__(256, 2) void gemm_mma_kernel(const float* __restrict__ A,
                                                          const float* __restrict__ W,
                                                          const float* __restrict__ R,
                                                          float* __restrict__ C,
                                                          int M, int K, int N, int lda){
    __shared__ uint32_t As[2][2048];
    __shared__ uint32_t Bs[2][2048];
    const int bm = blockIdx.y * 128;
    const int bn = blockIdx.x * 128;
    const int t  = threadIdx.x;
    float acc[4][4][4];
    #pragma unroll
    for (int i = 0; i < 4; i++)
        #pragma unroll
        for (int j = 0; j < 4; j++)
            #pragma unroll
            for (int q = 0; q < 4; q++) acc[i][j][q] = 0.f;
    gemm_mainloop(A, W, As, Bs, bm, bn, t, 0, K, N, lda, acc);
    gemm_epilogue(C, R, bm, bn, t, N, acc);
}

// ---------------- split-K GEMM ----------------
__global__ __launch_bounds__(256, 2) void gemm_mma_splitk_kernel(const float* __restrict__ A,
                                                                 const float* __restrict__ W,
                                                                 float* __restrict__ Cpart,
                                                                 int M, int K, int KH,
                                                                 int N, int lda){
    __shared__ uint32_t As[2][2048];
    __shared__ uint32_t Bs[2][2048];
    const int bm = blockIdx.y * 128;
    const int bn = blockIdx.x * 128;
    const int t  = threadIdx.x;
    const int z  = blockIdx.z;
    const int K0   = z * KH;
    const int Kend = (K0 + KH < K) ? (K0 + KH) : K;
    float acc[4][4][4];
    #pragma unroll
    for (int i = 0; i < 4; i++)
        #pragma unroll
        for (int j = 0; j < 4; j++)
            #pragma unroll
            for (int q = 0; q < 4; q++) acc[i][j][q] = 0.f;
    gemm_mainloop(A, W, As, Bs, bm, bn, t, K0, Kend, N, lda, acc);
    gemm_epilogue(Cpart + (size_t)z*M*N, nullptr, bm, bn, t, N, acc);
}

// ---------------- fused attention: 32 rows/block, reg-Q, single-exp softmax ----------------
#define AT_ROWS 32
#define KV_LD 68
#define ATTN_SMEM ((AT_ROWS*SEQ + 2*64*KV_LD + 32) * (int)sizeof(float))

__global__ __launch_bounds__(512) void attn_kernel(const float* __restrict__ qkv,
                                                   float* __restrict__ o){
    extern __shared__ float sm[];
    float* S    = sm;
    float* Ks   = S  + AT_ROWS*SEQ;
    float* Vs   = Ks + 64*KV_LD;
    float* Sinv = Vs + 64*KV_LD;
    int it = blockIdx.x;
    int h  = blockIdx.y;
    int b  = blockIdx.z;
    int i0 = it * AT_ROWS;
    int tid = threadIdx.x;
    int row = tid >> 4;
    int q16 = tid & 15;
    int i   = i0 + row;

    float4 qreg[16];
    {
        const float4* qp = reinterpret_cast<const float4*>(
            qkv + (size_t)(b*SEQ + i)*QKV_N + h*DH);
        #pragma unroll
        for (int c = 0; c < 16; c++){
            float4 v = qp[c];
            v.x *= 0.125f; v.y *= 0.125f; v.z *= 0.125f; v.w *= 0.125f;
            qreg[c] = v;
        }
    }

    int njt = (i0 + AT_ROWS - 1)/64 + 1;

    for (int jt = 0; jt < njt; jt++){
        for (int idx = tid; idx < 64*16; idx += 512){
            int r = idx >> 4, c4 = idx & 15;
            float4 v = *reinterpret_cast<const float4*>(
                qkv + (size_t)(b*SEQ + jt*64 + r)*QKV_N + DIM + c4*4);
            *reinterpret_cast<float4*>(&Ks[r*KV_LD + c4*4]) = v;
        }
        __syncthreads();
        #pragma unroll
        for (int jj = 0; jj < 4; jj++){
            int jl = jj*16 + q16;
            int j  = jt*64 + jl;
            float acc = 0.f;
            #pragma unroll
            for (int c = 0; c < 16; c++){
                float4 k4 = *reinterpret_cast<const float4*>(&Ks[jl*KV_LD + c*4]);
                acc += qreg[c].x*k4.x + qreg[c].y*k4.y + qreg[c].z*k4.z + qreg[c].w*k4.w;
            }
            S[row*SEQ + j] = (j <= i) ? (acc + g_bias[(i-j)*HEADS + h]) : -FLT_MAX;
        }
        __syncthreads();
    }

    int warp = tid >> 5, lane = tid & 31;
    int ncol = njt * 64;
    for (int r = warp*2; r < warp*2 + 2; r++){
        int ii = i0 + r;
        float mx = -FLT_MAX;
        for (int j = lane; j <= ii; j += 32) mx = fmaxf(mx, S[r*SEQ + j]);
        #pragma unroll
        for (int off = 16; off; off >>= 1) mx = fmaxf(mx, __shfl_xor_sync(0xffffffffu, mx, off));
        float sum = 0.f;
        for (int j = lane; j < ncol; j += 32){
            float p = __expf(S[r*SEQ + j] - mx);
            S[r*SEQ + j] = p;
            sum += p;
        }
        #pragma unroll
        for (int off = 16; off; off >>= 1) sum += __shfl_xor_sync(0xffffffffu, sum, off);
        if (lane == 0) Sinv[r] = __frcp_rn(sum);
    }
    __syncthreads();

    float4 accv = make_float4(0.f, 0.f, 0.f, 0.f);
    for (int jt = 0; jt < njt; jt++){
        for (int idx = tid; idx < 64*16; idx += 512){
            int r = idx >> 4, c4 = idx & 15;
            float4 v = *reinterpret_cast<const float4*>(
                qkv + (size_t)(b*SEQ + jt*64 + r)*QKV_N + DIM + DH + c4*4);
            *reinterpret_cast<float4*>(&Vs[r*KV_LD + c4*4]) = v;
        }
        __syncthreads();
        #pragma unroll 4
        for (int j4 = 0; j4 < 16; j4++){
            float4 s4 = *reinterpret_cast<const float4*>(&S[row*SEQ + jt*64 + j4*4]);
            float4 v0 = *reinterpret_cast<const float4*>(&Vs[(j4*4+0)*KV_LD + q16*4]);
            float4 v1 = *reinterpret_cast<const float4*>(&Vs[(j4*4+1)*KV_LD + q16*4]);
            float4 v2 = *reinterpret_cast<const float4*>(&Vs[(j4*4+2)*KV_LD + q16*4]);
            float4 v3 = *reinterpret_cast<const float4*>(&Vs[(j4*4+3)*KV_LD + q16*4]);
            accv.x += s4.x*v0.x + s4.y*v1.x + s4.z*v2.x + s4.w*v3.x;
            accv.y += s4.x*v0.y + s4.y*v1.y + s4.z*v2.y + s4.w*v3.y;
            accv.z += s4.x*v0.z + s4.y*v1.z + s4.z*v2.z + s4.w*v3.z;
            accv.w += s4.x*v0.w + s4.y*v1.w + s4.z*v2.w + s4.w*v3.w;
        }
        __syncthreads();
    }
    float inv = Sinv[row];
    accv.x *= inv; accv.y *= inv; accv.z *= inv; accv.w *= inv;
    *reinterpret_cast<float4*>(o + (size_t)(b*SEQ + i)*DIM + h*DH + q16*4) = accv;
}

// ---------------- fused causal conv(3) + GELU-GLU + LayerNorm ----------------
__global__ __launch_bounds__(256) void convglu_ln_kernel(const float* __restrict__ g1,
                                                         const float* __restrict__ cw,
                                                         const float* __restrict__ lng,
                                                         float* __restrict__ out){
    __shared__ float hbuf[INNER];
    __shared__ float sh1[8], sh2[8];
    int t = blockIdx.x;
    int n = t & (SEQ-1);
    size_t base = (size_t)t * INNER2;
    float s = 0.f, s2 = 0.f;
    for (int c = threadIdx.x; c < INNER; c += blockDim.x){
        float w0 = cw[c*3+0], w1 = cw[c*3+1], w2 = cw[c*3+2];
        float a = ((n >= 2) ? g1[base - 2*(size_t)INNER2 + c] : 0.f) * w0
                + ((n >= 1) ? g1[base -   (size_t)INNER2 + c] : 0.f) * w1
                +              g1[base + c] * w2;
        int cg = c + INNER;
        float v0 = cw[cg*3+0], v1 = cw[cg*3+1], v2 = cw[cg*3+2];
        float g = ((n >= 2) ? g1[base - 2*(size_t)INNER2 + cg] : 0.f) * v0
                + ((n >= 1) ? g1[base -   (size_t)INNER2 + cg] : 0.f) * v1
                +              g1[base + cg] * v2;
        float gg = 0.5f * g * (1.f + erff(g * 0.70710678118654752f));
        float h = gg * a;
        hbuf[c] = h;
        s += h; s2 += h*h;
    }
    int lane = threadIdx.x & 31, warp = threadIdx.x >> 5;
    #pragma unroll
    for (int off = 16; off; off >>= 1){
        s  += __shfl_xor_sync(0xffffffffu, s,  off);
        s2 += __shfl_xor_sync(0xffffffffu, s2, off);
    }
    if (lane == 0){ sh1[warp] = s; sh2[warp] = s2; }
    __syncthreads();
    if (warp == 0){
        s  = (lane < 8) ? sh1[lane] : 0.f;
        s2 = (lane < 8) ? sh2[lane] : 0.f;
        #pragma unroll
        for (int off = 4; off; off >>= 1){
            s  += __shfl_xor_sync(0xffffffffu, s,  off);
            s2 += __shfl_xor_sync(0xffffffffu, s2, off);
        }
        if (lane == 0){ sh1[0] = s; sh2[0] = s2; }
    }
    __syncthreads();
    float m   = sh1[0] / (float)INNER;
    float var = sh2[0] / (float)INNER - m*m;
    float r   = rsqrtf(var + 1e-5f);
    for (int c = threadIdx.x; c < INNER; c += blockDim.x)
        out[(size_t)t*INNER_P + c] = (hbuf[c] - m) * r * lng[c];
    for (int c = INNER + threadIdx.x; c < INNER_P; c += blockDim.x)
        out[(size_t)t*INNER_P + c] = 0.f;
}

// ---------------- launch helpers ----------------
static inline void run_gemm(const float* A, const float* W, const float* R, float* C,
                            int M, int K, int N, int lda){
    dim3 grid((N + 127)/128, M/128);
    gemm_mma_kernel<<<grid, 256>>>(A, W, R, C, M, K, N, lda);
}
static inline void run_gemm_splitk_raw(const float* A, const float* W, float* Cpart,
                                       int M, int K, int KH, int N, int lda){
    dim3 grid((N + 127)/128, M/128, 2);
    gemm_mma_splitk_kernel<<<grid, 256>>>(A, W, Cpart, M, K, KH, N, lda);
}

extern "C" void kernel_launch(void* const* d_in, const int* in_sizes, int n_in,
                              void* d_out, int out_size){
    const float* x     = (const float*)d_in[0];
    const float* rel   = (const float*)d_in[1];
    const float* qn_g  = (const float*)d_in[2];
    const float* wq    = (const float*)d_in[3];
    const float* wkv   = (const float*)d_in[4];
    const float* wo    = (const float*)d_in[5];
    const float* ln1g  = (const float*)d_in[6];
    const float* w1    = (const float*)d_in[7];
    const float* convw = (const float*)d_in[8];
    const float* ln2g  = (const float*)d_in[9];
    const float* w2    = (const float*)d_in[10];
    const float* fing  = (const float*)d_in[11];
    float* out = (float*)d_out;

    float *px, *ph, *pqkv, *po, *pg1, *ph3, *pwqkv, *ppart;
    cudaGetSymbolAddress((void**)&px,    g_x);
    cudaGetSymbolAddress((void**)&ph,    g_h);
    cudaGetSymbolAddress((void**)&pqkv,  g_qkv);
    cudaGetSymbolAddress((void**)&po,    g_o);
    cudaGetSymbolAddress((void**)&pg1,   g_g1);
    cudaGetSymbolAddress((void**)&ph3,   g_h3);
    cudaGetSymbolAddress((void**)&pwqkv, g_wqkv);
    cudaGetSymbolAddress((void**)&ppart, g_part);

    cudaFuncSetAttribute(attn_kernel, cudaFuncAttributeMaxDynamicSharedMemorySize, ATTN_SMEM);

    bias_kernel<<<(SEQ*HEADS + 255)/256, 256>>>(rel);
    scale_copy_kernel<<<(TOK*DIM + 255)/256, 256>>>(x, px, TOK*DIM);
    {
        size_t tot = (size_t)DEPTH*DIM*QKV_N;
        pack_qkv_kernel<<<(unsigned)((tot + 255)/256), 256>>>(wq, wkv, pwqkv);
    }

    // first LN (layer 0 qn)
    ln1024_kernel<<<TOK, 256>>>(px, qn_g, ph);

    for (int l = 0; l < DEPTH; l++){
        // attention block
        run_gemm_splitk_raw(ph, pwqkv + (size_t)l*DIM*QKV_N, ppart, TOK, DIM, 512, QKV_N, DIM);
        {
            int n4 = (int)(((size_t)TOK*QKV_N) >> 2);
            combine_kernel<<<(n4 + 255)/256, 256>>>(ppart, nullptr, pqkv, n4);
        }
        dim3 agrid(SEQ/AT_ROWS, HEADS, BATCH);
        attn_kernel<<<agrid, 512, ATTN_SMEM>>>(pqkv, po);
        // wo GEMM -> fused combine(+residual) + LN(ln1g)
        run_gemm_splitk_raw(po, wo + (size_t)l*DIM*DIM, ppart, TOK, DIM, 512, DIM, DIM);
        combine_ln_kernel<<<TOK, 256>>>(ppart, px, px, ln1g + l*DIM, ph);

        // conv-GLU MLP block
        run_gemm(ph, w1 + (size_t)l*DIM*INNER2, nullptr, pg1, TOK, DIM, INNER2, DIM);
        convglu_ln_kernel<<<TOK, 256>>>(pg1, convw + (size_t)l*INNER2*3,
                                        ln2g + (size_t)l*INNER, ph3);
        // w2 GEMM -> fused combine(+residual) + LN(next qn / final)
        run_gemm_splitk_raw(ph3, w2 + (size_t)l*INNER*DIM, ppart, TOK, INNER, 1376, DIM, INNER_P);
        if (l + 1 < DEPTH){
            combine_ln_kernel<<<TOK, 256>>>(ppart, px, px, qn_g + (l+1)*DIM, ph);
        } else {
            combine_ln_kernel<<<TOK, 256>>>(ppart, px, px, fing, out);
        }
    }
}